// round 1
// baseline (speedup 1.0000x reference)
#include <cuda_runtime.h>

#define N_NODES 50000
#define N_EDGES 1600000
#define IN_DIM  128
#define HID_DIM 256
#define OUT_DIM 128

// ---------------- device scratch (no allocations allowed) ----------------
__device__ float g_agg1[(size_t)N_NODES * IN_DIM];   // 25.6 MB
__device__ float g_h   [(size_t)N_NODES * HID_DIM];  // 51.2 MB
__device__ float g_agg2[(size_t)N_NODES * HID_DIM];  // 51.2 MB
__device__ float g_deg [N_NODES];                    // 0.2 MB
__device__ int   g_is64;

// ---------------- utility: zero a float buffer (float4 granularity) ------
__global__ void zero_kernel(float* __restrict__ p, int n4) {
    float4 z = make_float4(0.f, 0.f, 0.f, 0.f);
    float4* p4 = reinterpret_cast<float4*>(p);
    for (int i = blockIdx.x * blockDim.x + threadIdx.x; i < n4;
         i += gridDim.x * blockDim.x)
        p4[i] = z;
}

// ---------------- detect int64 vs int32 edge_index -----------------------
// If edge_index is genuinely int64, every high 32-bit word is 0 (ids < 50000).
// If it is int32 (JAX x64 disabled), odd words are random ids — the chance
// that four of them are all zero is (1/50000)^4 ~ 0.
__global__ void detect_kernel(const int* __restrict__ ei32) {
    if (threadIdx.x == 0 && blockIdx.x == 0) {
        g_is64 = (ei32[1] == 0 && ei32[3] == 0 && ei32[5] == 0 && ei32[7] == 0) ? 1 : 0;
    }
}

// ---------------- edge scatter: agg[dst] += feat[src], deg[dst] += 1 -----
// One warp per edge. DIMV = dim/4 float4 chunks (32 or 64).
template<int DIMV, bool COUNT_DEG>
__global__ void scatter_kernel(const float* __restrict__ feat,
                               const void* __restrict__ ei_raw,
                               float* __restrict__ agg,
                               float* __restrict__ deg)
{
    int warp = (blockIdx.x * blockDim.x + threadIdx.x) >> 5;
    int lane = threadIdx.x & 31;
    if (warp >= N_EDGES) return;

    long long src, dst;
    if (g_is64) {
        const long long* e = reinterpret_cast<const long long*>(ei_raw);
        src = e[warp];
        dst = e[N_EDGES + warp];
    } else {
        const int* e = reinterpret_cast<const int*>(ei_raw);
        src = e[warp];
        dst = e[N_EDGES + warp];
    }

    const float4* f4 = reinterpret_cast<const float4*>(feat + src * (size_t)(DIMV * 4));
    float* a = agg + dst * (size_t)(DIMV * 4);

#pragma unroll
    for (int c = lane; c < DIMV; c += 32) {
        float4 v = f4[c];
        atomicAdd(a + c * 4 + 0, v.x);
        atomicAdd(a + c * 4 + 1, v.y);
        atomicAdd(a + c * 4 + 2, v.z);
        atomicAdd(a + c * 4 + 3, v.w);
    }
    if (COUNT_DEG && lane == 0) atomicAdd(deg + dst, 1.0f);
}

// ---------------- fused SAGE GEMM ----------------------------------------
// C[M,N] = act( (A1 * (1/max(deg,1))) @ Wl  +  A2 @ Wr  + bias )
// Implemented as a single K=(K1+K2) GEMM over a virtually concatenated A.
// 64x64 tile, BK=16, 256 threads, 4x4 micro-tile per thread.
template<int K1, int K2, int N, bool RELU>
__global__ __launch_bounds__(256)
void gemm_fused(const float* __restrict__ A1,
                const float* __restrict__ A2,
                const float* __restrict__ deg,
                const float* __restrict__ Wl,   // [K1, N]
                const float* __restrict__ Wr,   // [K2, N]
                const float* __restrict__ bias, // [N]
                float* __restrict__ C, int M)
{
    const int BM = 64, BN = 64, BK = 16;
    __shared__ float As[BK][BM + 4];  // As[k][m]
    __shared__ float Bs[BK][BN + 4];  // Bs[k][n]

    int tid = threadIdx.x;
    int tx = tid & 15;        // 0..15 -> n micro
    int ty = tid >> 4;        // 0..15 -> m micro
    int m0 = blockIdx.x * BM;
    int n0 = blockIdx.y * BN;

    // A loading: each thread loads 4 consecutive k for one row
    int la_m = tid >> 2;             // 0..63
    int la_k = (tid & 3) * 4;        // 0,4,8,12
    // B loading: each thread loads 4 consecutive n for one k
    int lb_k = tid >> 4;             // 0..15
    int lb_n = (tid & 15) * 4;       // 0..60

    int arow = m0 + la_m;
    bool arow_ok = arow < M;
    float scale = 1.0f;
    if (arow_ok) scale = 1.0f / fmaxf(deg[arow], 1.0f);

    float acc[4][4] = {};

    for (int kk = 0; kk < K1 + K2; kk += BK) {
        // ---- load A tile (scaled mean part for k<K1, raw x part after) ----
        float4 av = make_float4(0.f, 0.f, 0.f, 0.f);
        if (arow_ok) {
            int k = kk + la_k;
            if (k < K1) {
                av = *reinterpret_cast<const float4*>(A1 + (size_t)arow * K1 + k);
                av.x *= scale; av.y *= scale; av.z *= scale; av.w *= scale;
            } else {
                av = *reinterpret_cast<const float4*>(A2 + (size_t)arow * K2 + (k - K1));
            }
        }
        As[la_k + 0][la_m] = av.x;
        As[la_k + 1][la_m] = av.y;
        As[la_k + 2][la_m] = av.z;
        As[la_k + 3][la_m] = av.w;

        // ---- load B tile ----
        {
            int k = kk + lb_k;
            const float* Wrow = (k < K1) ? (Wl + (size_t)k * N)
                                         : (Wr + (size_t)(k - K1) * N);
            float4 bv = *reinterpret_cast<const float4*>(Wrow + n0 + lb_n);
            Bs[lb_k][lb_n + 0] = bv.x;
            Bs[lb_k][lb_n + 1] = bv.y;
            Bs[lb_k][lb_n + 2] = bv.z;
            Bs[lb_k][lb_n + 3] = bv.w;
        }
        __syncthreads();

#pragma unroll
        for (int k2 = 0; k2 < BK; k2++) {
            float a[4], b[4];
#pragma unroll
            for (int i = 0; i < 4; i++) a[i] = As[k2][ty * 4 + i];
#pragma unroll
            for (int j = 0; j < 4; j++) b[j] = Bs[k2][tx * 4 + j];
#pragma unroll
            for (int i = 0; i < 4; i++)
#pragma unroll
                for (int j = 0; j < 4; j++)
                    acc[i][j] += a[i] * b[j];
        }
        __syncthreads();
    }

    // ---- epilogue: bias (+ relu) ----
#pragma unroll
    for (int i = 0; i < 4; i++) {
        int row = m0 + ty * 4 + i;
        if (row >= M) continue;
#pragma unroll
        for (int j = 0; j < 4; j++) {
            int col = n0 + tx * 4 + j;
            float v = acc[i][j] + bias[col];
            if (RELU) v = fmaxf(v, 0.0f);
            C[(size_t)row * N + col] = v;
        }
    }
}

// ---------------- launcher -------------------------------------------------
extern "C" void kernel_launch(void* const* d_in, const int* in_sizes, int n_in,
                              void* d_out, int out_size)
{
    const float* x   = (const float*)d_in[0];
    const void*  ei  = d_in[1];
    const float* Wl1 = (const float*)d_in[2];
    const float* bl1 = (const float*)d_in[3];
    const float* Wr1 = (const float*)d_in[4];
    const float* Wl2 = (const float*)d_in[5];
    const float* bl2 = (const float*)d_in[6];
    const float* Wr2 = (const float*)d_in[7];
    float* out = (float*)d_out;

    float *agg1, *h, *agg2, *deg;
    cudaGetSymbolAddress((void**)&agg1, g_agg1);
    cudaGetSymbolAddress((void**)&h,    g_h);
    cudaGetSymbolAddress((void**)&agg2, g_agg2);
    cudaGetSymbolAddress((void**)&deg,  g_deg);

    // dtype detection for edge_index
    detect_kernel<<<1, 32>>>((const int*)ei);

    // zero accumulators
    zero_kernel<<<1024, 256>>>(agg1, (N_NODES * IN_DIM) / 4);
    zero_kernel<<<1024, 256>>>(agg2, (N_NODES * HID_DIM) / 4);
    zero_kernel<<<256, 256>>>(deg, N_NODES / 4);

    // ---- layer 1 ----
    {
        const int threads = 256;
        long long total = (long long)N_EDGES * 32;
        int blocks = (int)((total + threads - 1) / threads);
        scatter_kernel<IN_DIM / 4, true><<<blocks, threads>>>(x, ei, agg1, deg);
    }
    {
        dim3 grid((N_NODES + 63) / 64, HID_DIM / 64);
        gemm_fused<IN_DIM, IN_DIM, HID_DIM, true><<<grid, 256>>>(
            agg1, x, deg, Wl1, Wr1, bl1, h, N_NODES);
    }

    // ---- layer 2 ----
    {
        const int threads = 256;
        long long total = (long long)N_EDGES * 32;
        int blocks = (int)((total + threads - 1) / threads);
        scatter_kernel<HID_DIM / 4, false><<<blocks, threads>>>(h, ei, agg2, deg);
    }
    {
        dim3 grid((N_NODES + 63) / 64, OUT_DIM / 64);
        gemm_fused<HID_DIM, HID_DIM, OUT_DIM, false><<<grid, 256>>>(
            agg2, h, deg, Wl2, Wr2, bl2, out, N_NODES);
    }
}

// round 2
// speedup vs baseline: 3.2057x; 3.2057x over previous
#include <cuda_runtime.h>

#define N_NODES 50000
#define N_EDGES 1600000
#define IN_DIM  128
#define HID_DIM 256
#define OUT_DIM 128

// ---------------- device scratch (no allocations allowed) ----------------
__device__ float g_mean1[(size_t)N_NODES * IN_DIM];   // 25.6 MB  mean-agg of x
__device__ float g_h    [(size_t)N_NODES * HID_DIM];  // 51.2 MB  layer-1 output
__device__ float g_cat  [(size_t)N_NODES * HID_DIM];  // 51.2 MB  [p | z] for layer 2
__device__ int   g_deg  [N_NODES];
__device__ int   g_rowoff[N_NODES + 1];
__device__ int   g_cursor[N_NODES];
__device__ int   g_csr  [N_EDGES];
__device__ int   g_is64;

// ---------------- detect int64 vs int32 edge_index -----------------------
__global__ void detect_kernel(const int* __restrict__ ei32) {
    if (threadIdx.x == 0 && blockIdx.x == 0) {
        g_is64 = (ei32[1] == 0 && ei32[3] == 0 && ei32[5] == 0 && ei32[7] == 0) ? 1 : 0;
    }
}

__global__ void zero_deg_kernel(int* __restrict__ deg) {
    int i = blockIdx.x * blockDim.x + threadIdx.x;
    if (i < N_NODES) deg[i] = 0;
}

// ---------------- histogram of in-degrees ---------------------------------
__global__ void hist_kernel(const void* __restrict__ ei, int* __restrict__ deg) {
    int i = blockIdx.x * blockDim.x + threadIdx.x;
    if (i >= N_EDGES) return;
    int dst;
    if (g_is64) dst = (int)reinterpret_cast<const long long*>(ei)[N_EDGES + i];
    else        dst = reinterpret_cast<const int*>(ei)[N_EDGES + i];
    atomicAdd(&deg[dst], 1);
}

// ---------------- exclusive scan (single block, 1024 threads) -------------
__global__ void scan_kernel(const int* __restrict__ deg,
                            int* __restrict__ row_off,
                            int* __restrict__ cursor) {
    __shared__ int sums[1024];
    const int CH = (N_NODES + 1023) / 1024;
    int tid = threadIdx.x;
    int start = tid * CH;
    int s = 0;
    for (int i = 0; i < CH; i++) {
        int idx = start + i;
        if (idx < N_NODES) s += deg[idx];
    }
    sums[tid] = s;
    __syncthreads();
    // Hillis-Steele inclusive scan
    for (int off = 1; off < 1024; off <<= 1) {
        int v = (tid >= off) ? sums[tid - off] : 0;
        __syncthreads();
        sums[tid] += v;
        __syncthreads();
    }
    int run = (tid == 0) ? 0 : sums[tid - 1];
    for (int i = 0; i < CH; i++) {
        int idx = start + i;
        if (idx < N_NODES) {
            row_off[idx] = run;
            cursor[idx] = run;
            run += deg[idx];
        }
    }
    if (tid == 1023) row_off[N_NODES] = run;
}

// ---------------- fill CSR adjacency --------------------------------------
__global__ void fill_kernel(const void* __restrict__ ei,
                            int* __restrict__ cursor,
                            int* __restrict__ csr) {
    int i = blockIdx.x * blockDim.x + threadIdx.x;
    if (i >= N_EDGES) return;
    int src, dst;
    if (g_is64) {
        const long long* e = reinterpret_cast<const long long*>(ei);
        src = (int)e[i];
        dst = (int)e[N_EDGES + i];
    } else {
        const int* e = reinterpret_cast<const int*>(ei);
        src = e[i];
        dst = e[N_EDGES + i];
    }
    int pos = atomicAdd(&cursor[dst], 1);
    csr[pos] = src;
}

// ---------------- gather-mean: out[n] = mean_{s in N(n)} feat[s] ----------
// One warp per node; each lane owns one float4 of the 128-dim row.
__global__ void gather_mean128(const float* __restrict__ feat,
                               const int* __restrict__ row_off,
                               const int* __restrict__ csr,
                               float* __restrict__ outm) {
    int node = blockIdx.x * (blockDim.x >> 5) + (threadIdx.x >> 5);
    int lane = threadIdx.x & 31;
    if (node >= N_NODES) return;
    int s0 = row_off[node], s1 = row_off[node + 1];
    const float4* f4 = reinterpret_cast<const float4*>(feat);
    float4 acc = make_float4(0.f, 0.f, 0.f, 0.f);
    for (int j = s0; j < s1; j += 32) {
        int n = min(32, s1 - j);
        int sj = (lane < n) ? csr[j + lane] : 0;
#pragma unroll 4
        for (int t = 0; t < n; t++) {
            int s = __shfl_sync(0xffffffffu, sj, t);
            float4 v = f4[(size_t)s * 32 + lane];
            acc.x += v.x; acc.y += v.y; acc.z += v.z; acc.w += v.w;
        }
    }
    float inv = 1.0f / (float)max(s1 - s0, 1);
    acc.x *= inv; acc.y *= inv; acc.z *= inv; acc.w *= inv;
    reinterpret_cast<float4*>(outm)[(size_t)node * 32 + lane] = acc;
}

// ---------------- final gather: out[n] = mean(p[src]) + z[n] --------------
// cat layout: row of 256 floats = [p(128) | z(128)] = 64 float4
__global__ void gather_final128(const float* __restrict__ cat,
                                const int* __restrict__ row_off,
                                const int* __restrict__ csr,
                                float* __restrict__ out) {
    int node = blockIdx.x * (blockDim.x >> 5) + (threadIdx.x >> 5);
    int lane = threadIdx.x & 31;
    if (node >= N_NODES) return;
    int s0 = row_off[node], s1 = row_off[node + 1];
    const float4* c4 = reinterpret_cast<const float4*>(cat);
    float4 acc = make_float4(0.f, 0.f, 0.f, 0.f);
    for (int j = s0; j < s1; j += 32) {
        int n = min(32, s1 - j);
        int sj = (lane < n) ? csr[j + lane] : 0;
#pragma unroll 4
        for (int t = 0; t < n; t++) {
            int s = __shfl_sync(0xffffffffu, sj, t);
            float4 v = c4[(size_t)s * 64 + lane];
            acc.x += v.x; acc.y += v.y; acc.z += v.z; acc.w += v.w;
        }
    }
    float inv = 1.0f / (float)max(s1 - s0, 1);
    float4 z = c4[(size_t)node * 64 + 32 + lane];
    float4 r;
    r.x = acc.x * inv + z.x;
    r.y = acc.y * inv + z.y;
    r.z = acc.z * inv + z.z;
    r.w = acc.w * inv + z.w;
    reinterpret_cast<float4*>(out)[(size_t)node * 32 + lane] = r;
}

// ---------------- GEMM 1: concat along K ----------------------------------
// C = act( [A1 | A2] @ [B1 ; B2] + bias ),  128x128x8 tile, 8x8 micro.
template<int K1, int K2, int N, bool RELU>
__global__ __launch_bounds__(256, 2)
void gemm_catK(const float* __restrict__ A1, const float* __restrict__ A2,
               const float* __restrict__ B1, const float* __restrict__ B2,
               const float* __restrict__ bias,
               float* __restrict__ C, int M)
{
    const int BM = 128, BN = 128, BK = 8;
    __shared__ float As[BK][BM + 4];
    __shared__ float Bs[BK][BN + 4];

    int tid = threadIdx.x;
    int m0 = blockIdx.x * BM, n0 = blockIdx.y * BN;
    int tx = tid & 15, ty = tid >> 4;

    int la_r = tid >> 1, la_k = (tid & 1) * 4;   // A: row, 4-k chunk
    int lb_k = tid >> 5, lb_n = (tid & 31) * 4;  // B: k, 4-n chunk
    int arow = m0 + la_r;
    bool aok = arow < M;

    float acc[8][8];
#pragma unroll
    for (int i = 0; i < 8; i++)
#pragma unroll
        for (int j = 0; j < 8; j++) acc[i][j] = 0.f;

    for (int kk = 0; kk < K1 + K2; kk += BK) {
        float4 av = make_float4(0.f, 0.f, 0.f, 0.f);
        int ka = kk + la_k;
        if (aok) {
            if (ka < K1) av = *reinterpret_cast<const float4*>(A1 + (size_t)arow * K1 + ka);
            else         av = *reinterpret_cast<const float4*>(A2 + (size_t)arow * K2 + (ka - K1));
        }
        As[la_k + 0][la_r] = av.x;
        As[la_k + 1][la_r] = av.y;
        As[la_k + 2][la_r] = av.z;
        As[la_k + 3][la_r] = av.w;

        int kb = kk + lb_k;
        const float* Brow = (kb < K1) ? (B1 + (size_t)kb * N)
                                      : (B2 + (size_t)(kb - K1) * N);
        *reinterpret_cast<float4*>(&Bs[lb_k][lb_n]) =
            *reinterpret_cast<const float4*>(Brow + n0 + lb_n);
        __syncthreads();

#pragma unroll
        for (int k2 = 0; k2 < BK; k2++) {
            float a[8], b[8];
            *reinterpret_cast<float4*>(a)     = *reinterpret_cast<float4*>(&As[k2][ty * 4]);
            *reinterpret_cast<float4*>(a + 4) = *reinterpret_cast<float4*>(&As[k2][ty * 4 + 64]);
            *reinterpret_cast<float4*>(b)     = *reinterpret_cast<float4*>(&Bs[k2][tx * 4]);
            *reinterpret_cast<float4*>(b + 4) = *reinterpret_cast<float4*>(&Bs[k2][tx * 4 + 64]);
#pragma unroll
            for (int i = 0; i < 8; i++)
#pragma unroll
                for (int j = 0; j < 8; j++)
                    acc[i][j] += a[i] * b[j];
        }
        __syncthreads();
    }

#pragma unroll
    for (int i = 0; i < 8; i++) {
        int row = m0 + ((i < 4) ? (ty * 4 + i) : (64 + ty * 4 + i - 4));
        if (row >= M) continue;
#pragma unroll
        for (int jh = 0; jh < 2; jh++) {
            int col = n0 + tx * 4 + jh * 64;
            float4 v;
            v.x = acc[i][jh * 4 + 0] + bias[col + 0];
            v.y = acc[i][jh * 4 + 1] + bias[col + 1];
            v.z = acc[i][jh * 4 + 2] + bias[col + 2];
            v.w = acc[i][jh * 4 + 3] + bias[col + 3];
            if (RELU) {
                v.x = fmaxf(v.x, 0.f); v.y = fmaxf(v.y, 0.f);
                v.z = fmaxf(v.z, 0.f); v.w = fmaxf(v.w, 0.f);
            }
            *reinterpret_cast<float4*>(C + (size_t)row * N + col) = v;
        }
    }
}

// ---------------- GEMM 2: concat along N ----------------------------------
// C[:, :NH]  = A @ B1            (p, no bias)
// C[:, NH:]  = A @ B2 + bias     (z)
template<int K, int NH>   // output width = 2*NH
__global__ __launch_bounds__(256, 2)
void gemm_catN(const float* __restrict__ A,
               const float* __restrict__ B1, const float* __restrict__ B2,
               const float* __restrict__ bias,
               float* __restrict__ C, int M)
{
    const int BM = 128, BN = 128, BK = 8;
    const int N = 2 * NH;
    __shared__ float As[BK][BM + 4];
    __shared__ float Bs[BK][BN + 4];

    int tid = threadIdx.x;
    int m0 = blockIdx.x * BM, n0 = blockIdx.y * BN;
    bool right = (n0 >= NH);     // BN == NH, so each block is entirely one half
    const float* B = right ? B2 : B1;
    int nb0 = right ? (n0 - NH) : n0;

    int tx = tid & 15, ty = tid >> 4;
    int la_r = tid >> 1, la_k = (tid & 1) * 4;
    int lb_k = tid >> 5, lb_n = (tid & 31) * 4;
    int arow = m0 + la_r;
    bool aok = arow < M;

    float acc[8][8];
#pragma unroll
    for (int i = 0; i < 8; i++)
#pragma unroll
        for (int j = 0; j < 8; j++) acc[i][j] = 0.f;

    for (int kk = 0; kk < K; kk += BK) {
        float4 av = make_float4(0.f, 0.f, 0.f, 0.f);
        if (aok) av = *reinterpret_cast<const float4*>(A + (size_t)arow * K + kk + la_k);
        As[la_k + 0][la_r] = av.x;
        As[la_k + 1][la_r] = av.y;
        As[la_k + 2][la_r] = av.z;
        As[la_k + 3][la_r] = av.w;

        *reinterpret_cast<float4*>(&Bs[lb_k][lb_n]) =
            *reinterpret_cast<const float4*>(B + (size_t)(kk + lb_k) * NH + nb0 + lb_n);
        __syncthreads();

#pragma unroll
        for (int k2 = 0; k2 < BK; k2++) {
            float a[8], b[8];
            *reinterpret_cast<float4*>(a)     = *reinterpret_cast<float4*>(&As[k2][ty * 4]);
            *reinterpret_cast<float4*>(a + 4) = *reinterpret_cast<float4*>(&As[k2][ty * 4 + 64]);
            *reinterpret_cast<float4*>(b)     = *reinterpret_cast<float4*>(&Bs[k2][tx * 4]);
            *reinterpret_cast<float4*>(b + 4) = *reinterpret_cast<float4*>(&Bs[k2][tx * 4 + 64]);
#pragma unroll
            for (int i = 0; i < 8; i++)
#pragma unroll
                for (int j = 0; j < 8; j++)
                    acc[i][j] += a[i] * b[j];
        }
        __syncthreads();
    }

#pragma unroll
    for (int i = 0; i < 8; i++) {
        int row = m0 + ((i < 4) ? (ty * 4 + i) : (64 + ty * 4 + i - 4));
        if (row >= M) continue;
#pragma unroll
        for (int jh = 0; jh < 2; jh++) {
            int coll = tx * 4 + jh * 64;      // local col within the half
            int col = n0 + coll;              // global col in C
            float4 v;
            float bx = right ? bias[coll + 0] : 0.f;
            float by = right ? bias[coll + 1] : 0.f;
            float bz = right ? bias[coll + 2] : 0.f;
            float bw = right ? bias[coll + 3] : 0.f;
            v.x = acc[i][jh * 4 + 0] + bx;
            v.y = acc[i][jh * 4 + 1] + by;
            v.z = acc[i][jh * 4 + 2] + bz;
            v.w = acc[i][jh * 4 + 3] + bw;
            *reinterpret_cast<float4*>(C + (size_t)row * N + col) = v;
        }
    }
}

// ---------------- launcher -------------------------------------------------
extern "C" void kernel_launch(void* const* d_in, const int* in_sizes, int n_in,
                              void* d_out, int out_size)
{
    const float* x   = (const float*)d_in[0];
    const void*  ei  = d_in[1];
    const float* Wl1 = (const float*)d_in[2];
    const float* bl1 = (const float*)d_in[3];
    const float* Wr1 = (const float*)d_in[4];
    const float* Wl2 = (const float*)d_in[5];
    const float* bl2 = (const float*)d_in[6];
    const float* Wr2 = (const float*)d_in[7];
    float* out = (float*)d_out;

    float *mean1, *h, *cat;
    int *deg, *rowoff, *cursor, *csr;
    cudaGetSymbolAddress((void**)&mean1,  g_mean1);
    cudaGetSymbolAddress((void**)&h,      g_h);
    cudaGetSymbolAddress((void**)&cat,    g_cat);
    cudaGetSymbolAddress((void**)&deg,    g_deg);
    cudaGetSymbolAddress((void**)&rowoff, g_rowoff);
    cudaGetSymbolAddress((void**)&cursor, g_cursor);
    cudaGetSymbolAddress((void**)&csr,    g_csr);

    // ---- CSR build ----
    detect_kernel<<<1, 32>>>((const int*)ei);
    zero_deg_kernel<<<(N_NODES + 255) / 256, 256>>>(deg);
    hist_kernel<<<(N_EDGES + 255) / 256, 256>>>(ei, deg);
    scan_kernel<<<1, 1024>>>(deg, rowoff, cursor);
    fill_kernel<<<(N_EDGES + 255) / 256, 256>>>(ei, cursor, csr);

    // ---- layer 1: mean-aggregate x, then fused GEMM ----
    {
        int warps_per_block = 8;
        int blocks = (N_NODES + warps_per_block - 1) / warps_per_block;
        gather_mean128<<<blocks, warps_per_block * 32>>>(x, rowoff, csr, mean1);
    }
    {
        dim3 grid((N_NODES + 127) / 128, HID_DIM / 128);
        gemm_catK<IN_DIM, IN_DIM, HID_DIM, true><<<grid, 256>>>(
            mean1, x, Wl1, Wr1, bl1, h, N_NODES);
    }

    // ---- layer 2: GEMM first (p = h@Wl2, z = h@Wr2 + b), then aggregate p ----
    {
        dim3 grid((N_NODES + 127) / 128, (2 * OUT_DIM) / 128);
        gemm_catN<HID_DIM, OUT_DIM><<<grid, 256>>>(h, Wl2, Wr2, bl2, cat, N_NODES);
    }
    {
        int warps_per_block = 8;
        int blocks = (N_NODES + warps_per_block - 1) / warps_per_block;
        gather_final128<<<blocks, warps_per_block * 32>>>(cat, rowoff, csr, out);
    }
}

// round 4
// speedup vs baseline: 4.3678x; 1.3625x over previous
#include <cuda_runtime.h>
#include <cuda_bf16.h>
#include <cstdint>

#define N_NODES 50000
#define N_EDGES 1600000
#define IN_DIM  128
#define HID_DIM 256
#define OUT_DIM 128

// ---------------- device scratch (no allocations allowed) ----------------
__device__ float g_mean1[(size_t)N_NODES * IN_DIM];   // mean-agg of x
__device__ float g_h    [(size_t)N_NODES * HID_DIM];  // layer-1 output
__device__ float g_cat  [(size_t)N_NODES * HID_DIM];  // [p | z] for layer 2
__device__ int   g_deg  [N_NODES];
__device__ int   g_rowoff[N_NODES + 1];
__device__ int   g_cursor[N_NODES];
__device__ int   g_csr  [N_EDGES];
__device__ int   g_is64;
__device__ int   g_blocksum[128];
__device__ int   g_blockoff[128];
__device__ int   g_total;
// pre-built B' weights: [n=256][k'=768] bf16, k' = [Bhi(256) | Blo(256) | Bhi(256)]
__device__ __align__(16) __nv_bfloat16 g_BW1[256 * 768];
__device__ __align__(16) __nv_bfloat16 g_BW2[256 * 768];

// ---------------- mma helpers ----------------------------------------
__device__ __forceinline__ uint32_t smem_u32(const void* p) {
    uint32_t a;
    asm("{ .reg .u64 t; cvta.to.shared.u64 t, %1; cvt.u32.u64 %0, t; }"
        : "=r"(a) : "l"(p));
    return a;
}
__device__ __forceinline__ void ldsm_x4(uint32_t* r, uint32_t addr) {
    asm volatile("ldmatrix.sync.aligned.m8n8.x4.shared.b16 {%0,%1,%2,%3}, [%4];"
        : "=r"(r[0]), "=r"(r[1]), "=r"(r[2]), "=r"(r[3]) : "r"(addr));
}
__device__ __forceinline__ void ldsm_x2(uint32_t* r, uint32_t addr) {
    asm volatile("ldmatrix.sync.aligned.m8n8.x2.shared.b16 {%0,%1}, [%2];"
        : "=r"(r[0]), "=r"(r[1]) : "r"(addr));
}
__device__ __forceinline__ void mma_bf16(float* d, const uint32_t* a, const uint32_t* b) {
    asm volatile("mma.sync.aligned.m16n8k16.row.col.f32.bf16.bf16.f32 "
        "{%0,%1,%2,%3}, {%4,%5,%6,%7}, {%8,%9}, {%0,%1,%2,%3};"
        : "+f"(d[0]), "+f"(d[1]), "+f"(d[2]), "+f"(d[3])
        : "r"(a[0]), "r"(a[1]), "r"(a[2]), "r"(a[3]), "r"(b[0]), "r"(b[1]));
}

// ---------------- detect int64 vs int32 edge_index -----------------------
__global__ void detect_kernel(const int* __restrict__ ei32) {
    if (threadIdx.x == 0 && blockIdx.x == 0)
        g_is64 = (ei32[1] == 0 && ei32[3] == 0 && ei32[5] == 0 && ei32[7] == 0) ? 1 : 0;
}

__global__ void zero_deg_kernel(int* __restrict__ deg) {
    int i = blockIdx.x * blockDim.x + threadIdx.x;
    if (i < N_NODES) deg[i] = 0;
}

__global__ void hist_kernel(const void* __restrict__ ei, int* __restrict__ deg) {
    int i = blockIdx.x * blockDim.x + threadIdx.x;
    if (i >= N_EDGES) return;
    int dst;
    if (g_is64) dst = (int)reinterpret_cast<const long long*>(ei)[N_EDGES + i];
    else        dst = reinterpret_cast<const int*>(ei)[N_EDGES + i];
    atomicAdd(&deg[dst], 1);
}

// ---------------- 3-phase scan --------------------------------------------
#define SCAN_BLK 512
#define N_SCAN_BLOCKS ((N_NODES + SCAN_BLK - 1) / SCAN_BLK)  // 98

__global__ void scan_phase1(const int* __restrict__ deg, int* __restrict__ bsum) {
    __shared__ int sm[SCAN_BLK];
    int i = blockIdx.x * SCAN_BLK + threadIdx.x;
    sm[threadIdx.x] = (i < N_NODES) ? deg[i] : 0;
    __syncthreads();
    for (int s = SCAN_BLK / 2; s > 0; s >>= 1) {
        if (threadIdx.x < s) sm[threadIdx.x] += sm[threadIdx.x + s];
        __syncthreads();
    }
    if (threadIdx.x == 0) bsum[blockIdx.x] = sm[0];
}

__global__ void scan_phase2(const int* __restrict__ bsum, int* __restrict__ boff,
                            int* __restrict__ total) {
    __shared__ int sm[128];
    int t = threadIdx.x;
    sm[t] = (t < N_SCAN_BLOCKS) ? bsum[t] : 0;
    __syncthreads();
    for (int off = 1; off < 128; off <<= 1) {
        int v = (t >= off) ? sm[t - off] : 0;
        __syncthreads();
        sm[t] += v;
        __syncthreads();
    }
    if (t < N_SCAN_BLOCKS) boff[t] = (t == 0) ? 0 : sm[t - 1];
    if (t == 127) *total = sm[127];
}

__global__ void scan_phase3(const int* __restrict__ deg, const int* __restrict__ boff,
                            const int* __restrict__ total,
                            int* __restrict__ rowoff, int* __restrict__ cursor) {
    __shared__ int sm[SCAN_BLK];
    int i = blockIdx.x * SCAN_BLK + threadIdx.x;
    int v = (i < N_NODES) ? deg[i] : 0;
    sm[threadIdx.x] = v;
    __syncthreads();
    for (int off = 1; off < SCAN_BLK; off <<= 1) {
        int u = (threadIdx.x >= off) ? sm[threadIdx.x - off] : 0;
        __syncthreads();
        sm[threadIdx.x] += u;
        __syncthreads();
    }
    if (i < N_NODES) {
        int excl = boff[blockIdx.x] + sm[threadIdx.x] - v;
        rowoff[i] = excl;
        cursor[i] = excl;
    }
    if (blockIdx.x == gridDim.x - 1 && threadIdx.x == SCAN_BLK - 1)
        rowoff[N_NODES] = *total;
}

__global__ void fill_kernel(const void* __restrict__ ei,
                            int* __restrict__ cursor, int* __restrict__ csr) {
    int i = blockIdx.x * blockDim.x + threadIdx.x;
    if (i >= N_EDGES) return;
    int src, dst;
    if (g_is64) {
        const long long* e = reinterpret_cast<const long long*>(ei);
        src = (int)e[i]; dst = (int)e[N_EDGES + i];
    } else {
        const int* e = reinterpret_cast<const int*>(ei);
        src = e[i]; dst = e[N_EDGES + i];
    }
    int pos = atomicAdd(&cursor[dst], 1);
    csr[pos] = src;
}

// ---------------- weight prep: transpose + bf16 hi/lo, build B' [256][768] --
__global__ void prep_weights(const float* __restrict__ Wl1, const float* __restrict__ Wr1,
                             const float* __restrict__ Wl2, const float* __restrict__ Wr2,
                             __nv_bfloat16* __restrict__ BW1,
                             __nv_bfloat16* __restrict__ BW2) {
    int idx = blockIdx.x * blockDim.x + threadIdx.x;  // n*768 + kp
    if (idx >= 256 * 768) return;
    int n = idx / 768, kp = idx % 768;
    int seg = kp >> 8, k = kp & 255;
    // layer1: K = [mean(128) | x(128)] -> k<128: Wl1[k][n] else Wr1[k-128][n]
    float w1 = (k < 128) ? Wl1[k * 256 + n] : Wr1[(k - 128) * 256 + n];
    // layer2: N = [p(128) | z(128)] -> n<128: Wl2[k][n] else Wr2[k][n-128]
    float w2 = (n < 128) ? Wl2[k * 128 + n] : Wr2[k * 128 + (n - 128)];
    __nv_bfloat16 h1 = __float2bfloat16(w1);
    __nv_bfloat16 h2 = __float2bfloat16(w2);
    BW1[idx] = (seg == 1) ? __float2bfloat16(w1 - __bfloat162float(h1)) : h1;
    BW2[idx] = (seg == 1) ? __float2bfloat16(w2 - __bfloat162float(h2)) : h2;
}

// ---------------- gather-mean: out[n] = mean_{s in N(n)} feat[s] ----------
__global__ void gather_mean128(const float* __restrict__ feat,
                               const int* __restrict__ row_off,
                               const int* __restrict__ csr,
                               float* __restrict__ outm) {
    int node = blockIdx.x * (blockDim.x >> 5) + (threadIdx.x >> 5);
    int lane = threadIdx.x & 31;
    if (node >= N_NODES) return;
    int s0 = row_off[node], s1 = row_off[node + 1];
    const float4* f4 = reinterpret_cast<const float4*>(feat);
    float4 acc = make_float4(0.f, 0.f, 0.f, 0.f);
    for (int j = s0; j < s1; j += 32) {
        int n = min(32, s1 - j);
        int sj = (lane < n) ? csr[j + lane] : 0;
#pragma unroll 4
        for (int t = 0; t < n; t++) {
            int s = __shfl_sync(0xffffffffu, sj, t);
            float4 v = f4[(size_t)s * 32 + lane];
            acc.x += v.x; acc.y += v.y; acc.z += v.z; acc.w += v.w;
        }
    }
    float inv = 1.0f / (float)max(s1 - s0, 1);
    acc.x *= inv; acc.y *= inv; acc.z *= inv; acc.w *= inv;
    reinterpret_cast<float4*>(outm)[(size_t)node * 32 + lane] = acc;
}

__global__ void gather_final128(const float* __restrict__ cat,
                                const int* __restrict__ row_off,
                                const int* __restrict__ csr,
                                float* __restrict__ out) {
    int node = blockIdx.x * (blockDim.x >> 5) + (threadIdx.x >> 5);
    int lane = threadIdx.x & 31;
    if (node >= N_NODES) return;
    int s0 = row_off[node], s1 = row_off[node + 1];
    const float4* c4 = reinterpret_cast<const float4*>(cat);
    float4 acc = make_float4(0.f, 0.f, 0.f, 0.f);
    for (int j = s0; j < s1; j += 32) {
        int n = min(32, s1 - j);
        int sj = (lane < n) ? csr[j + lane] : 0;
#pragma unroll 4
        for (int t = 0; t < n; t++) {
            int s = __shfl_sync(0xffffffffu, sj, t);
            float4 v = c4[(size_t)s * 64 + lane];
            acc.x += v.x; acc.y += v.y; acc.z += v.z; acc.w += v.w;
        }
    }
    float inv = 1.0f / (float)max(s1 - s0, 1);
    float4 z = c4[(size_t)node * 64 + 32 + lane];
    float4 r;
    r.x = acc.x * inv + z.x;
    r.y = acc.y * inv + z.y;
    r.z = acc.z * inv + z.z;
    r.w = acc.w * inv + z.w;
    reinterpret_cast<float4*>(out)[(size_t)node * 32 + lane] = r;
}

// ---------------- bf16x3 mma.sync GEMM -------------------------------------
// C[M,256] = act( A' @ B'^T + bias ), virtual K' = 768:
//   A' = [Ahi(256) | Ahi(256) | Alo(256)],  B' = [Bhi | Blo | Bhi]  (prebuilt)
// Block tile 128x128 (grid.y = 2 picks the n half). 8 warps: wm=wid&3 (32 rows),
// wn=wid>>2 (64 cols). BK'=32 per chunk, 24 chunks, register-prefetch pipeline.
// mode 0 (layer1): A = [mean1 | x] (each stride 128), relu, bias on all cols
// mode 1 (layer2): A = h (stride 256), bias only on cols>=128, no relu
__global__ __launch_bounds__(256)
void sage_gemm_mma(const float* __restrict__ A1, const float* __restrict__ A2,
                   const __nv_bfloat16* __restrict__ BW,
                   const float* __restrict__ bias,
                   float* __restrict__ C, int M, int mode)
{
    __shared__ __align__(16) char sA[128 * 80];   // [row][k32] bf16, 80B padded
    __shared__ __align__(16) char sB[128 * 80];

    int tid = threadIdx.x;
    int lane = tid & 31, wid = tid >> 5;
    int wm = wid & 3, wn = wid >> 2;
    int m0 = blockIdx.x * 128, n0 = blockIdx.y * 128;

    uint32_t sAa = smem_u32(sA);
    uint32_t sBa = smem_u32(sB);

    int srow = tid >> 1, shalf = tid & 1;   // staging: row 0..127, k-half 0/1
    int grow = m0 + srow;

    float acc[2][8][4];
#pragma unroll
    for (int i = 0; i < 2; i++)
#pragma unroll
        for (int j = 0; j < 8; j++)
#pragma unroll
            for (int q = 0; q < 4; q++) acc[i][j][q] = 0.f;

    float4 pa[4];
    uint4  pb[2];

#define LOAD_CHUNK(cc) do { \
    int kc = ((cc) & 7) * 32; \
    const float* Asrc; int astr, acol; \
    if (mode == 0) { \
        if (kc < 128) { Asrc = A1; acol = kc; } \
        else          { Asrc = A2; acol = kc - 128; } \
        astr = 128; \
    } else { Asrc = A1; astr = 256; acol = kc; } \
    if (grow < M) { \
        const float4* ap = reinterpret_cast<const float4*>( \
            Asrc + (size_t)grow * astr + acol + shalf * 16); \
        pa[0] = ap[0]; pa[1] = ap[1]; pa[2] = ap[2]; pa[3] = ap[3]; \
    } else { \
        pa[0] = pa[1] = pa[2] = pa[3] = make_float4(0.f, 0.f, 0.f, 0.f); \
    } \
    const uint4* bp = reinterpret_cast<const uint4*>( \
        BW + (size_t)(n0 + srow) * 768 + (cc) * 32 + shalf * 16); \
    pb[0] = bp[0]; pb[1] = bp[1]; \
} while (0)

#define STORE_CHUNK(cc) do { \
    bool lo_ = ((cc) >> 3) == 2; \
    const float* f_ = reinterpret_cast<const float*>(pa); \
    uint32_t w_[8]; \
    _Pragma("unroll") \
    for (int i_ = 0; i_ < 8; i_++) { \
        float v0_ = f_[i_ * 2], v1_ = f_[i_ * 2 + 1]; \
        __nv_bfloat16 h0_ = __float2bfloat16(v0_); \
        __nv_bfloat16 h1_ = __float2bfloat16(v1_); \
        if (lo_) { \
            h0_ = __float2bfloat16(v0_ - __bfloat162float(h0_)); \
            h1_ = __float2bfloat16(v1_ - __bfloat162float(h1_)); \
        } \
        w_[i_] = (uint32_t)__bfloat16_as_ushort(h0_) | \
                 ((uint32_t)__bfloat16_as_ushort(h1_) << 16); \
    } \
    uint4* da_ = reinterpret_cast<uint4*>(sA + srow * 80 + shalf * 32); \
    da_[0] = make_uint4(w_[0], w_[1], w_[2], w_[3]); \
    da_[1] = make_uint4(w_[4], w_[5], w_[6], w_[7]); \
    uint4* db_ = reinterpret_cast<uint4*>(sB + srow * 80 + shalf * 32); \
    db_[0] = pb[0]; \
    db_[1] = pb[1]; \
} while (0)

    LOAD_CHUNK(0);

    for (int c = 0; c < 24; c++) {
        STORE_CHUNK(c);
        __syncthreads();
        if (c < 23) LOAD_CHUNK(c + 1);

#pragma unroll
        for (int kh = 0; kh < 2; kh++) {
            uint32_t af[2][4], bf[8][2];
#pragma unroll
            for (int mt = 0; mt < 2; mt++)
                ldsm_x4(af[mt], sAa + (uint32_t)(wm * 32 + mt * 16 + (lane & 15)) * 80
                               + kh * 32 + (lane >> 4) * 16);
#pragma unroll
            for (int nt = 0; nt < 8; nt++)
                ldsm_x2(bf[nt], sBa + (uint32_t)(wn * 64 + nt * 8 + (lane & 7)) * 80
                               + kh * 32 + ((lane >> 3) & 1) * 16);
#pragma unroll
            for (int mt = 0; mt < 2; mt++)
#pragma unroll
                for (int nt = 0; nt < 8; nt++)
                    mma_bf16(acc[mt][nt], af[mt], bf[nt]);
        }
        __syncthreads();
    }

    // ---- epilogue ----
    int g = lane >> 2, t = lane & 3;
#pragma unroll
    for (int mt = 0; mt < 2; mt++) {
        int r0 = m0 + wm * 32 + mt * 16 + g;
#pragma unroll
        for (int nt = 0; nt < 8; nt++) {
            int col = n0 + wn * 64 + nt * 8 + t * 2;
            float bx = 0.f, by = 0.f;
            if (mode == 0) { bx = bias[col]; by = bias[col + 1]; }
            else if (col >= 128) { bx = bias[col - 128]; by = bias[col - 127]; }
            float v0 = acc[mt][nt][0] + bx, v1 = acc[mt][nt][1] + by;
            float v2 = acc[mt][nt][2] + bx, v3 = acc[mt][nt][3] + by;
            if (mode == 0) {
                v0 = fmaxf(v0, 0.f); v1 = fmaxf(v1, 0.f);
                v2 = fmaxf(v2, 0.f); v3 = fmaxf(v3, 0.f);
            }
            if (r0 < M)
                *reinterpret_cast<float2*>(C + (size_t)r0 * 256 + col) = make_float2(v0, v1);
            if (r0 + 8 < M)
                *reinterpret_cast<float2*>(C + (size_t)(r0 + 8) * 256 + col) = make_float2(v2, v3);
        }
    }
}

// ---------------- launcher -------------------------------------------------
extern "C" void kernel_launch(void* const* d_in, const int* in_sizes, int n_in,
                              void* d_out, int out_size)
{
    const float* x   = (const float*)d_in[0];
    const void*  ei  = d_in[1];
    const float* Wl1 = (const float*)d_in[2];
    const float* bl1 = (const float*)d_in[3];
    const float* Wr1 = (const float*)d_in[4];
    const float* Wl2 = (const float*)d_in[5];
    const float* bl2 = (const float*)d_in[6];
    const float* Wr2 = (const float*)d_in[7];
    float* out = (float*)d_out;

    float *mean1, *h, *cat;
    int *deg, *rowoff, *cursor, *csr, *bsum, *boff, *total;
    __nv_bfloat16 *BW1, *BW2;
    cudaGetSymbolAddress((void**)&mean1,  g_mean1);
    cudaGetSymbolAddress((void**)&h,      g_h);
    cudaGetSymbolAddress((void**)&cat,    g_cat);
    cudaGetSymbolAddress((void**)&deg,    g_deg);
    cudaGetSymbolAddress((void**)&rowoff, g_rowoff);
    cudaGetSymbolAddress((void**)&cursor, g_cursor);
    cudaGetSymbolAddress((void**)&csr,    g_csr);
    cudaGetSymbolAddress((void**)&bsum,   g_blocksum);
    cudaGetSymbolAddress((void**)&boff,   g_blockoff);
    cudaGetSymbolAddress((void**)&total,  g_total);
    cudaGetSymbolAddress((void**)&BW1,    g_BW1);
    cudaGetSymbolAddress((void**)&BW2,    g_BW2);

    // ---- CSR build ----
    detect_kernel<<<1, 32>>>((const int*)ei);
    zero_deg_kernel<<<(N_NODES + 255) / 256, 256>>>(deg);
    hist_kernel<<<(N_EDGES + 255) / 256, 256>>>(ei, deg);
    scan_phase1<<<N_SCAN_BLOCKS, SCAN_BLK>>>(deg, bsum);
    scan_phase2<<<1, 128>>>(bsum, boff, total);
    scan_phase3<<<N_SCAN_BLOCKS, SCAN_BLK>>>(deg, boff, total, rowoff, cursor);
    fill_kernel<<<(N_EDGES + 255) / 256, 256>>>(ei, cursor, csr);

    // ---- weight prep ----
    prep_weights<<<(256 * 768 + 255) / 256, 256>>>(Wl1, Wr1, Wl2, Wr2, BW1, BW2);

    // ---- layer 1 ----
    {
        int wpb = 8;
        int blocks = (N_NODES + wpb - 1) / wpb;
        gather_mean128<<<blocks, wpb * 32>>>(x, rowoff, csr, mean1);
    }
    {
        dim3 grid((N_NODES + 127) / 128, 2);
        sage_gemm_mma<<<grid, 256>>>(mean1, x, BW1, bl1, h, N_NODES, 0);
    }

    // ---- layer 2 ----
    {
        dim3 grid((N_NODES + 127) / 128, 2);
        sage_gemm_mma<<<grid, 256>>>(h, nullptr, BW2, bl2, cat, N_NODES, 1);
    }
    {
        int wpb = 8;
        int blocks = (N_NODES + wpb - 1) / wpb;
        gather_final128<<<blocks, wpb * 32>>>(cat, rowoff, csr, out);
    }
}

// round 5
// speedup vs baseline: 4.6313x; 1.0603x over previous
#include <cuda_runtime.h>
#include <cuda_bf16.h>
#include <cstdint>

#define N_NODES 50000
#define N_EDGES 1600000
#define IN_DIM  128
#define HID_DIM 256
#define OUT_DIM 128

// ---------------- device scratch (no allocations allowed) ----------------
__device__ float g_mean1[(size_t)N_NODES * IN_DIM];   // mean-agg of x
__device__ float g_h    [(size_t)N_NODES * HID_DIM];  // layer-1 output
__device__ float g_cat  [(size_t)N_NODES * HID_DIM];  // [p | z] for layer 2
__device__ int   g_deg  [N_NODES];
__device__ int   g_rowoff[N_NODES + 1];
__device__ int   g_cursor[N_NODES];
__device__ int   g_csr  [N_EDGES];
__device__ int   g_is64;
__device__ int   g_blocksum[128];
__device__ int   g_blockoff[128];
__device__ int   g_total;
// pre-built B' weights: [n=256][k'=768] bf16, k' = [Bhi(256) | Blo(256) | Bhi(256)]
__device__ __align__(16) __nv_bfloat16 g_BW1[256 * 768];
__device__ __align__(16) __nv_bfloat16 g_BW2[256 * 768];

// ---------------- mma helpers ----------------------------------------
__device__ __forceinline__ uint32_t smem_u32(const void* p) {
    uint32_t a;
    asm("{ .reg .u64 t; cvta.to.shared.u64 t, %1; cvt.u32.u64 %0, t; }"
        : "=r"(a) : "l"(p));
    return a;
}
__device__ __forceinline__ void ldsm_x4(uint32_t* r, uint32_t addr) {
    asm volatile("ldmatrix.sync.aligned.m8n8.x4.shared.b16 {%0,%1,%2,%3}, [%4];"
        : "=r"(r[0]), "=r"(r[1]), "=r"(r[2]), "=r"(r[3]) : "r"(addr));
}
__device__ __forceinline__ void mma_bf16(float* d, const uint32_t* a, const uint32_t* b) {
    asm volatile("mma.sync.aligned.m16n8k16.row.col.f32.bf16.bf16.f32 "
        "{%0,%1,%2,%3}, {%4,%5,%6,%7}, {%8,%9}, {%0,%1,%2,%3};"
        : "+f"(d[0]), "+f"(d[1]), "+f"(d[2]), "+f"(d[3])
        : "r"(a[0]), "r"(a[1]), "r"(a[2]), "r"(a[3]), "r"(b[0]), "r"(b[1]));
}
__device__ __forceinline__ void cp_async16(uint32_t dst, const void* src) {
    asm volatile("cp.async.cg.shared.global [%0], [%1], 16;"
                 :: "r"(dst), "l"(src) : "memory");
}
#define CP_COMMIT() asm volatile("cp.async.commit_group;" ::: "memory")
#define CP_WAIT0()  asm volatile("cp.async.wait_group 0;" ::: "memory")

// ---------------- setup: detect dtype + zero deg + prep weights -----------
// prep: BW[n][kp], kp = seg*256 + k, seg0/2 = hi, seg1 = lo residual.
__global__ void setup_kernel(const int* __restrict__ ei32,
                             const float* __restrict__ Wl1, const float* __restrict__ Wr1,
                             const float* __restrict__ Wl2, const float* __restrict__ Wr2,
                             int* __restrict__ deg,
                             __nv_bfloat16* __restrict__ BW1,
                             __nv_bfloat16* __restrict__ BW2) {
    int idx = blockIdx.x * blockDim.x + threadIdx.x;
    if (idx == 0)
        g_is64 = (ei32[1] == 0 && ei32[3] == 0 && ei32[5] == 0 && ei32[7] == 0) ? 1 : 0;
    if (idx < N_NODES) deg[idx] = 0;
    if (idx < 256 * 768) {
        int n = idx / 768, kp = idx % 768;
        int seg = kp >> 8, k = kp & 255;
        float w1 = (k < 128) ? Wl1[k * 256 + n] : Wr1[(k - 128) * 256 + n];
        float w2 = (n < 128) ? Wl2[k * 128 + n] : Wr2[k * 128 + (n - 128)];
        __nv_bfloat16 h1 = __float2bfloat16(w1);
        __nv_bfloat16 h2 = __float2bfloat16(w2);
        BW1[idx] = (seg == 1) ? __float2bfloat16(w1 - __bfloat162float(h1)) : h1;
        BW2[idx] = (seg == 1) ? __float2bfloat16(w2 - __bfloat162float(h2)) : h2;
    }
}

__global__ void hist_kernel(const void* __restrict__ ei, int* __restrict__ deg) {
    int i = blockIdx.x * blockDim.x + threadIdx.x;
    if (i >= N_EDGES) return;
    int dst;
    if (g_is64) dst = (int)reinterpret_cast<const long long*>(ei)[N_EDGES + i];
    else        dst = reinterpret_cast<const int*>(ei)[N_EDGES + i];
    atomicAdd(&deg[dst], 1);
}

// ---------------- 3-phase scan --------------------------------------------
#define SCAN_BLK 512
#define N_SCAN_BLOCKS ((N_NODES + SCAN_BLK - 1) / SCAN_BLK)  // 98

__global__ void scan_phase1(const int* __restrict__ deg, int* __restrict__ bsum) {
    __shared__ int sm[SCAN_BLK];
    int i = blockIdx.x * SCAN_BLK + threadIdx.x;
    sm[threadIdx.x] = (i < N_NODES) ? deg[i] : 0;
    __syncthreads();
    for (int s = SCAN_BLK / 2; s > 0; s >>= 1) {
        if (threadIdx.x < s) sm[threadIdx.x] += sm[threadIdx.x + s];
        __syncthreads();
    }
    if (threadIdx.x == 0) bsum[blockIdx.x] = sm[0];
}

__global__ void scan_phase2(const int* __restrict__ bsum, int* __restrict__ boff,
                            int* __restrict__ total) {
    __shared__ int sm[128];
    int t = threadIdx.x;
    sm[t] = (t < N_SCAN_BLOCKS) ? bsum[t] : 0;
    __syncthreads();
    for (int off = 1; off < 128; off <<= 1) {
        int v = (t >= off) ? sm[t - off] : 0;
        __syncthreads();
        sm[t] += v;
        __syncthreads();
    }
    if (t < N_SCAN_BLOCKS) boff[t] = (t == 0) ? 0 : sm[t - 1];
    if (t == 127) *total = sm[127];
}

__global__ void scan_phase3(const int* __restrict__ deg, const int* __restrict__ boff,
                            const int* __restrict__ total,
                            int* __restrict__ rowoff, int* __restrict__ cursor) {
    __shared__ int sm[SCAN_BLK];
    int i = blockIdx.x * SCAN_BLK + threadIdx.x;
    int v = (i < N_NODES) ? deg[i] : 0;
    sm[threadIdx.x] = v;
    __syncthreads();
    for (int off = 1; off < SCAN_BLK; off <<= 1) {
        int u = (threadIdx.x >= off) ? sm[threadIdx.x - off] : 0;
        __syncthreads();
        sm[threadIdx.x] += u;
        __syncthreads();
    }
    if (i < N_NODES) {
        int excl = boff[blockIdx.x] + sm[threadIdx.x] - v;
        rowoff[i] = excl;
        cursor[i] = excl;
    }
    if (blockIdx.x == gridDim.x - 1 && threadIdx.x == SCAN_BLK - 1)
        rowoff[N_NODES] = *total;
}

__global__ void fill_kernel(const void* __restrict__ ei,
                            int* __restrict__ cursor, int* __restrict__ csr) {
    int i = blockIdx.x * blockDim.x + threadIdx.x;
    if (i >= N_EDGES) return;
    int src, dst;
    if (g_is64) {
        const long long* e = reinterpret_cast<const long long*>(ei);
        src = (int)e[i]; dst = (int)e[N_EDGES + i];
    } else {
        const int* e = reinterpret_cast<const int*>(ei);
        src = e[i]; dst = e[N_EDGES + i];
    }
    int pos = atomicAdd(&cursor[dst], 1);
    csr[pos] = src;
}

// ---------------- gather-mean: out[n] = mean_{s in N(n)} feat[s] ----------
__global__ void gather_mean128(const float* __restrict__ feat,
                               const int* __restrict__ row_off,
                               const int* __restrict__ csr,
                               float* __restrict__ outm) {
    int node = blockIdx.x * (blockDim.x >> 5) + (threadIdx.x >> 5);
    int lane = threadIdx.x & 31;
    if (node >= N_NODES) return;
    int s0 = row_off[node], s1 = row_off[node + 1];
    const float4* f4 = reinterpret_cast<const float4*>(feat);
    float4 acc = make_float4(0.f, 0.f, 0.f, 0.f);
    for (int j = s0; j < s1; j += 32) {
        int n = min(32, s1 - j);
        int sj = (lane < n) ? csr[j + lane] : 0;
#pragma unroll 4
        for (int t = 0; t < n; t++) {
            int s = __shfl_sync(0xffffffffu, sj, t);
            float4 v = f4[(size_t)s * 32 + lane];
            acc.x += v.x; acc.y += v.y; acc.z += v.z; acc.w += v.w;
        }
    }
    float inv = 1.0f / (float)max(s1 - s0, 1);
    acc.x *= inv; acc.y *= inv; acc.z *= inv; acc.w *= inv;
    reinterpret_cast<float4*>(outm)[(size_t)node * 32 + lane] = acc;
}

__global__ void gather_final128(const float* __restrict__ cat,
                                const int* __restrict__ row_off,
                                const int* __restrict__ csr,
                                float* __restrict__ out) {
    int node = blockIdx.x * (blockDim.x >> 5) + (threadIdx.x >> 5);
    int lane = threadIdx.x & 31;
    if (node >= N_NODES) return;
    int s0 = row_off[node], s1 = row_off[node + 1];
    const float4* c4 = reinterpret_cast<const float4*>(cat);
    float4 acc = make_float4(0.f, 0.f, 0.f, 0.f);
    for (int j = s0; j < s1; j += 32) {
        int n = min(32, s1 - j);
        int sj = (lane < n) ? csr[j + lane] : 0;
#pragma unroll 4
        for (int t = 0; t < n; t++) {
            int s = __shfl_sync(0xffffffffu, sj, t);
            float4 v = c4[(size_t)s * 64 + lane];
            acc.x += v.x; acc.y += v.y; acc.z += v.z; acc.w += v.w;
        }
    }
    float inv = 1.0f / (float)max(s1 - s0, 1);
    float4 z = c4[(size_t)node * 64 + 32 + lane];
    float4 r;
    r.x = acc.x * inv + z.x;
    r.y = acc.y * inv + z.y;
    r.z = acc.z * inv + z.z;
    r.w = acc.w * inv + z.w;
    reinterpret_cast<float4*>(out)[(size_t)node * 32 + lane] = r;
}

// ---------------- bf16x3 mma.sync GEMM, double-buffered --------------------
// C[M,256] = act( A' @ B'^T + bias ), virtual K' = 768 in 24 chunks of 32:
//   A' = [Ahi | Ahi | Alo],  B' = [Bhi | Blo | Bhi] (prebuilt, [n][k'] bf16)
// Block tile 128x128 (grid.y picks n half). 8 warps: wm=wid&3, wn=wid>>2.
// Pipeline: A via register prefetch + fp32->bf16 convert; B via cp.async.cg.
__global__ __launch_bounds__(256)
void sage_gemm_mma(const float* __restrict__ A1, const float* __restrict__ A2,
                   const __nv_bfloat16* __restrict__ BW,
                   const float* __restrict__ bias,
                   float* __restrict__ C, int M, int mode)
{
    __shared__ __align__(16) char sA[2][128 * 80];   // [row][32 bf16], 80B pitch
    __shared__ __align__(16) char sB[2][128 * 80];

    int tid = threadIdx.x;
    int lane = tid & 31, wid = tid >> 5;
    int wm = wid & 3, wn = wid >> 2;
    int m0 = blockIdx.x * 128, n0 = blockIdx.y * 128;

    uint32_t sAa[2] = { smem_u32(sA[0]), smem_u32(sA[1]) };
    uint32_t sBa[2] = { smem_u32(sB[0]), smem_u32(sB[1]) };

    int srow = tid >> 1, shalf = tid & 1;   // A staging: row 0..127, k-half 0/1
    int grow = m0 + srow;
    int brow = tid >> 2, bq = tid & 3;      // B staging: 16B quads

    float acc[2][8][4];
#pragma unroll
    for (int i = 0; i < 2; i++)
#pragma unroll
        for (int j = 0; j < 8; j++)
#pragma unroll
            for (int q = 0; q < 4; q++) acc[i][j][q] = 0.f;

    float4 pa[4];

#define LOAD_A(cc) do { \
    int kc = ((cc) & 7) * 32; \
    const float* Asrc; int astr, acol; \
    if (mode == 0) { \
        if (kc < 128) { Asrc = A1; acol = kc; } \
        else          { Asrc = A2; acol = kc - 128; } \
        astr = 128; \
    } else { Asrc = A1; astr = 256; acol = kc; } \
    if (grow < M) { \
        const float4* ap = reinterpret_cast<const float4*>( \
            Asrc + (size_t)grow * astr + acol + shalf * 16); \
        pa[0] = ap[0]; pa[1] = ap[1]; pa[2] = ap[2]; pa[3] = ap[3]; \
    } else { \
        pa[0] = pa[1] = pa[2] = pa[3] = make_float4(0.f, 0.f, 0.f, 0.f); \
    } \
} while (0)

#define STORE_A(cc, buf) do { \
    bool lo_ = ((cc) >> 3) == 2; \
    const float* f_ = reinterpret_cast<const float*>(pa); \
    uint32_t w_[8]; \
    _Pragma("unroll") \
    for (int i_ = 0; i_ < 8; i_++) { \
        float v0_ = f_[i_ * 2], v1_ = f_[i_ * 2 + 1]; \
        __nv_bfloat16 h0_ = __float2bfloat16(v0_); \
        __nv_bfloat16 h1_ = __float2bfloat16(v1_); \
        if (lo_) { \
            h0_ = __float2bfloat16(v0_ - __bfloat162float(h0_)); \
            h1_ = __float2bfloat16(v1_ - __bfloat162float(h1_)); \
        } \
        w_[i_] = (uint32_t)__bfloat16_as_ushort(h0_) | \
                 ((uint32_t)__bfloat16_as_ushort(h1_) << 16); \
    } \
    uint4* da_ = reinterpret_cast<uint4*>(sA[buf] + srow * 80 + shalf * 32); \
    da_[0] = make_uint4(w_[0], w_[1], w_[2], w_[3]); \
    da_[1] = make_uint4(w_[4], w_[5], w_[6], w_[7]); \
} while (0)

#define CP_B(cc, buf) do { \
    _Pragma("unroll") \
    for (int i_ = 0; i_ < 2; i_++) { \
        int r_ = brow + i_ * 64; \
        cp_async16(sBa[buf] + (uint32_t)r_ * 80 + bq * 16, \
                   BW + (size_t)(n0 + r_) * 768 + (cc) * 32 + bq * 8); \
    } \
    CP_COMMIT(); \
} while (0)

    // ---- prologue ----
    LOAD_A(0);
    STORE_A(0, 0);
    CP_B(0, 0);
    LOAD_A(1);
    CP_WAIT0();
    __syncthreads();

    for (int c = 0; c < 24; c++) {
        int cb = c & 1;
        if (c < 23) {
            STORE_A(c + 1, cb ^ 1);
            CP_B(c + 1, cb ^ 1);
            if (c < 22) LOAD_A(c + 2);
        }

        // ---- compute on buffer cb ----
#pragma unroll
        for (int kh = 0; kh < 2; kh++) {
            uint32_t af[2][4], bf[8][2];
#pragma unroll
            for (int mt = 0; mt < 2; mt++)
                ldsm_x4(af[mt], sAa[cb] + (uint32_t)(wm * 32 + mt * 16 + (lane & 15)) * 80
                               + kh * 32 + (lane >> 4) * 16);
#pragma unroll
            for (int np = 0; np < 4; np++) {
                uint32_t q[4];
                int r = wn * 64 + np * 16 + (lane & 7) + ((lane >> 4) & 1) * 8;
                int cOff = ((lane >> 3) & 1) * 16;
                ldsm_x4(q, sBa[cb] + (uint32_t)r * 80 + kh * 32 + cOff);
                bf[np * 2][0] = q[0]; bf[np * 2][1] = q[1];
                bf[np * 2 + 1][0] = q[2]; bf[np * 2 + 1][1] = q[3];
            }
#pragma unroll
            for (int mt = 0; mt < 2; mt++)
#pragma unroll
                for (int nt = 0; nt < 8; nt++)
                    mma_bf16(acc[mt][nt], af[mt], bf[nt]);
        }

        CP_WAIT0();
        __syncthreads();
    }

    // ---- epilogue ----
    int g = lane >> 2, t = lane & 3;
#pragma unroll
    for (int mt = 0; mt < 2; mt++) {
        int r0 = m0 + wm * 32 + mt * 16 + g;
#pragma unroll
        for (int nt = 0; nt < 8; nt++) {
            int col = n0 + wn * 64 + nt * 8 + t * 2;
            float bx = 0.f, by = 0.f;
            if (mode == 0) { bx = bias[col]; by = bias[col + 1]; }
            else if (col >= 128) { bx = bias[col - 128]; by = bias[col - 127]; }
            float v0 = acc[mt][nt][0] + bx, v1 = acc[mt][nt][1] + by;
            float v2 = acc[mt][nt][2] + bx, v3 = acc[mt][nt][3] + by;
            if (mode == 0) {
                v0 = fmaxf(v0, 0.f); v1 = fmaxf(v1, 0.f);
                v2 = fmaxf(v2, 0.f); v3 = fmaxf(v3, 0.f);
            }
            if (r0 < M)
                *reinterpret_cast<float2*>(C + (size_t)r0 * 256 + col) = make_float2(v0, v1);
            if (r0 + 8 < M)
                *reinterpret_cast<float2*>(C + (size_t)(r0 + 8) * 256 + col) = make_float2(v2, v3);
        }
    }
}

// ---------------- launcher -------------------------------------------------
extern "C" void kernel_launch(void* const* d_in, const int* in_sizes, int n_in,
                              void* d_out, int out_size)
{
    const float* x   = (const float*)d_in[0];
    const void*  ei  = d_in[1];
    const float* Wl1 = (const float*)d_in[2];
    const float* bl1 = (const float*)d_in[3];
    const float* Wr1 = (const float*)d_in[4];
    const float* Wl2 = (const float*)d_in[5];
    const float* bl2 = (const float*)d_in[6];
    const float* Wr2 = (const float*)d_in[7];
    float* out = (float*)d_out;

    float *mean1, *h, *cat;
    int *deg, *rowoff, *cursor, *csr, *bsum, *boff, *total;
    __nv_bfloat16 *BW1, *BW2;
    cudaGetSymbolAddress((void**)&mean1,  g_mean1);
    cudaGetSymbolAddress((void**)&h,      g_h);
    cudaGetSymbolAddress((void**)&cat,    g_cat);
    cudaGetSymbolAddress((void**)&deg,    g_deg);
    cudaGetSymbolAddress((void**)&rowoff, g_rowoff);
    cudaGetSymbolAddress((void**)&cursor, g_cursor);
    cudaGetSymbolAddress((void**)&csr,    g_csr);
    cudaGetSymbolAddress((void**)&bsum,   g_blocksum);
    cudaGetSymbolAddress((void**)&boff,   g_blockoff);
    cudaGetSymbolAddress((void**)&total,  g_total);
    cudaGetSymbolAddress((void**)&BW1,    g_BW1);
    cudaGetSymbolAddress((void**)&BW2,    g_BW2);

    // ---- setup (detect + zero deg + weight prep) ----
    setup_kernel<<<(256 * 768 + 255) / 256, 256>>>(
        (const int*)ei, Wl1, Wr1, Wl2, Wr2, deg, BW1, BW2);

    // ---- CSR build ----
    hist_kernel<<<(N_EDGES + 255) / 256, 256>>>(ei, deg);
    scan_phase1<<<N_SCAN_BLOCKS, SCAN_BLK>>>(deg, bsum);
    scan_phase2<<<1, 128>>>(bsum, boff, total);
    scan_phase3<<<N_SCAN_BLOCKS, SCAN_BLK>>>(deg, boff, total, rowoff, cursor);
    fill_kernel<<<(N_EDGES + 255) / 256, 256>>>(ei, cursor, csr);

    // ---- layer 1 ----
    {
        int wpb = 8;
        int blocks = (N_NODES + wpb - 1) / wpb;
        gather_mean128<<<blocks, wpb * 32>>>(x, rowoff, csr, mean1);
    }
    {
        dim3 grid((N_NODES + 127) / 128, 2);
        sage_gemm_mma<<<grid, 256>>>(mean1, x, BW1, bl1, h, N_NODES, 0);
    }

    // ---- layer 2 ----
    {
        dim3 grid((N_NODES + 127) / 128, 2);
        sage_gemm_mma<<<grid, 256>>>(h, nullptr, BW2, bl2, cat, N_NODES, 1);
    }
    {
        int wpb = 8;
        int blocks = (N_NODES + wpb - 1) / wpb;
        gather_final128<<<blocks, wpb * 32>>>(cat, rowoff, csr, out);
    }
}

// round 6
// speedup vs baseline: 4.7904x; 1.0344x over previous
#include <cuda_runtime.h>
#include <cuda_bf16.h>
#include <cuda_fp16.h>
#include <cstdint>

#define N_NODES 50000
#define N_EDGES 1600000
#define IN_DIM  128
#define HID_DIM 256
#define OUT_DIM 128

// ---------------- device scratch (no allocations allowed) ----------------
__device__ float g_mean1[(size_t)N_NODES * IN_DIM];   // mean-agg of x (fp32)
__device__ float g_h    [(size_t)N_NODES * HID_DIM];  // layer-1 output
__device__ float g_z    [(size_t)N_NODES * OUT_DIM];  // z = h@Wr2 + b
__device__ __half g_ph  [(size_t)N_NODES * OUT_DIM];  // p = h@Wl2 (fp16)
__device__ __half g_xh  [(size_t)N_NODES * IN_DIM];   // x in fp16
__device__ int   g_deg  [N_NODES];
__device__ int   g_rowoff[N_NODES + 1];
__device__ int   g_cursor[N_NODES];
__device__ int   g_csr  [N_EDGES];
__device__ int   g_is64;
__device__ int   g_blocksum[128];
__device__ int   g_blockoff[128];
__device__ int   g_total;
// pre-built B' weights: [n=256][k'=768] bf16, k' = [Bhi(256) | Blo(256) | Bhi(256)]
__device__ __align__(16) __nv_bfloat16 g_BW1[256 * 768];
__device__ __align__(16) __nv_bfloat16 g_BW2[256 * 768];

// ---------------- mma helpers ----------------------------------------
__device__ __forceinline__ uint32_t smem_u32(const void* p) {
    uint32_t a;
    asm("{ .reg .u64 t; cvta.to.shared.u64 t, %1; cvt.u32.u64 %0, t; }"
        : "=r"(a) : "l"(p));
    return a;
}
__device__ __forceinline__ void ldsm_x4(uint32_t* r, uint32_t addr) {
    asm volatile("ldmatrix.sync.aligned.m8n8.x4.shared.b16 {%0,%1,%2,%3}, [%4];"
        : "=r"(r[0]), "=r"(r[1]), "=r"(r[2]), "=r"(r[3]) : "r"(addr));
}
__device__ __forceinline__ void mma_bf16(float* d, const uint32_t* a, const uint32_t* b) {
    asm volatile("mma.sync.aligned.m16n8k16.row.col.f32.bf16.bf16.f32 "
        "{%0,%1,%2,%3}, {%4,%5,%6,%7}, {%8,%9}, {%0,%1,%2,%3};"
        : "+f"(d[0]), "+f"(d[1]), "+f"(d[2]), "+f"(d[3])
        : "r"(a[0]), "r"(a[1]), "r"(a[2]), "r"(a[3]), "r"(b[0]), "r"(b[1]));
}
__device__ __forceinline__ void cp_async16(uint32_t dst, const void* src) {
    asm volatile("cp.async.cg.shared.global [%0], [%1], 16;"
                 :: "r"(dst), "l"(src) : "memory");
}
#define CP_COMMIT() asm volatile("cp.async.commit_group;" ::: "memory")
#define CP_WAIT0()  asm volatile("cp.async.wait_group 0;" ::: "memory")

// ---------------- setup: detect + zero deg + prep weights + x->fp16 -------
__global__ void setup_kernel(const int* __restrict__ ei32,
                             const float* __restrict__ x,
                             const float* __restrict__ Wl1, const float* __restrict__ Wr1,
                             const float* __restrict__ Wl2, const float* __restrict__ Wr2,
                             int* __restrict__ deg,
                             __nv_bfloat16* __restrict__ BW1,
                             __nv_bfloat16* __restrict__ BW2,
                             __half* __restrict__ xh) {
    int idx = blockIdx.x * blockDim.x + threadIdx.x;
    if (idx == 0)
        g_is64 = (ei32[1] == 0 && ei32[3] == 0 && ei32[5] == 0 && ei32[7] == 0) ? 1 : 0;
    if (idx < N_NODES) deg[idx] = 0;
    if (idx < 256 * 768) {
        int n = idx / 768, kp = idx % 768;
        int seg = kp >> 8, k = kp & 255;
        float w1 = (k < 128) ? Wl1[k * 256 + n] : Wr1[(k - 128) * 256 + n];
        float w2 = (n < 128) ? Wl2[k * 128 + n] : Wr2[k * 128 + (n - 128)];
        __nv_bfloat16 h1 = __float2bfloat16(w1);
        __nv_bfloat16 h2 = __float2bfloat16(w2);
        BW1[idx] = (seg == 1) ? __float2bfloat16(w1 - __bfloat162float(h1)) : h1;
        BW2[idx] = (seg == 1) ? __float2bfloat16(w2 - __bfloat162float(h2)) : h2;
    }
    // x -> fp16, 4 elems per thread
    if (idx < (N_NODES * IN_DIM) / 4) {
        float4 v = reinterpret_cast<const float4*>(x)[idx];
        __half2 a = __floats2half2_rn(v.x, v.y);
        __half2 b = __floats2half2_rn(v.z, v.w);
        reinterpret_cast<uint2*>(xh)[idx] =
            make_uint2(*reinterpret_cast<uint32_t*>(&a), *reinterpret_cast<uint32_t*>(&b));
    }
}

__global__ void hist_kernel(const void* __restrict__ ei, int* __restrict__ deg) {
    int i = blockIdx.x * blockDim.x + threadIdx.x;
    if (i >= N_EDGES) return;
    int dst;
    if (g_is64) dst = (int)reinterpret_cast<const long long*>(ei)[N_EDGES + i];
    else        dst = reinterpret_cast<const int*>(ei)[N_EDGES + i];
    atomicAdd(&deg[dst], 1);
}

// ---------------- 3-phase scan --------------------------------------------
#define SCAN_BLK 512
#define N_SCAN_BLOCKS ((N_NODES + SCAN_BLK - 1) / SCAN_BLK)  // 98

__global__ void scan_phase1(const int* __restrict__ deg, int* __restrict__ bsum) {
    __shared__ int sm[SCAN_BLK];
    int i = blockIdx.x * SCAN_BLK + threadIdx.x;
    sm[threadIdx.x] = (i < N_NODES) ? deg[i] : 0;
    __syncthreads();
    for (int s = SCAN_BLK / 2; s > 0; s >>= 1) {
        if (threadIdx.x < s) sm[threadIdx.x] += sm[threadIdx.x + s];
        __syncthreads();
    }
    if (threadIdx.x == 0) bsum[blockIdx.x] = sm[0];
}

__global__ void scan_phase2(const int* __restrict__ bsum, int* __restrict__ boff,
                            int* __restrict__ total) {
    __shared__ int sm[128];
    int t = threadIdx.x;
    sm[t] = (t < N_SCAN_BLOCKS) ? bsum[t] : 0;
    __syncthreads();
    for (int off = 1; off < 128; off <<= 1) {
        int v = (t >= off) ? sm[t - off] : 0;
        __syncthreads();
        sm[t] += v;
        __syncthreads();
    }
    if (t < N_SCAN_BLOCKS) boff[t] = (t == 0) ? 0 : sm[t - 1];
    if (t == 127) *total = sm[127];
}

__global__ void scan_phase3(const int* __restrict__ deg, const int* __restrict__ boff,
                            const int* __restrict__ total,
                            int* __restrict__ rowoff, int* __restrict__ cursor) {
    __shared__ int sm[SCAN_BLK];
    int i = blockIdx.x * SCAN_BLK + threadIdx.x;
    int v = (i < N_NODES) ? deg[i] : 0;
    sm[threadIdx.x] = v;
    __syncthreads();
    for (int off = 1; off < SCAN_BLK; off <<= 1) {
        int u = (threadIdx.x >= off) ? sm[threadIdx.x - off] : 0;
        __syncthreads();
        sm[threadIdx.x] += u;
        __syncthreads();
    }
    if (i < N_NODES) {
        int excl = boff[blockIdx.x] + sm[threadIdx.x] - v;
        rowoff[i] = excl;
        cursor[i] = excl;
    }
    if (blockIdx.x == gridDim.x - 1 && threadIdx.x == SCAN_BLK - 1)
        rowoff[N_NODES] = *total;
}

__global__ void fill_kernel(const void* __restrict__ ei,
                            int* __restrict__ cursor, int* __restrict__ csr) {
    int i = blockIdx.x * blockDim.x + threadIdx.x;
    if (i >= N_EDGES) return;
    int src, dst;
    if (g_is64) {
        const long long* e = reinterpret_cast<const long long*>(ei);
        src = (int)e[i]; dst = (int)e[N_EDGES + i];
    } else {
        const int* e = reinterpret_cast<const int*>(ei);
        src = e[i]; dst = e[N_EDGES + i];
    }
    int pos = atomicAdd(&cursor[dst], 1);
    csr[pos] = src;
}

// ---------------- gather-mean (fp16 src): mean over neighbors -------------
// One warp per node; lane owns 4 cols (8B). 8-deep load batching.
__global__ void gather_mean_h(const __half* __restrict__ xh,
                              const int* __restrict__ row_off,
                              const int* __restrict__ csr,
                              float* __restrict__ outm) {
    int node = blockIdx.x * (blockDim.x >> 5) + (threadIdx.x >> 5);
    int lane = threadIdx.x & 31;
    if (node >= N_NODES) return;
    int s0 = row_off[node], s1 = row_off[node + 1];
    const uint2* x2 = reinterpret_cast<const uint2*>(xh);
    float ax = 0.f, ay = 0.f, az = 0.f, aw = 0.f;
    for (int j = s0; j < s1; j += 32) {
        int n = min(32, s1 - j);
        int sj = (lane < n) ? csr[j + lane] : 0;
        int t = 0;
        for (; t + 8 <= n; t += 8) {
            uint2 raw[8];
#pragma unroll
            for (int u = 0; u < 8; u++) {
                int s = __shfl_sync(0xffffffffu, sj, t + u);
                raw[u] = x2[(size_t)s * 32 + lane];
            }
#pragma unroll
            for (int u = 0; u < 8; u++) {
                float2 fa = __half22float2(*reinterpret_cast<__half2*>(&raw[u].x));
                float2 fb = __half22float2(*reinterpret_cast<__half2*>(&raw[u].y));
                ax += fa.x; ay += fa.y; az += fb.x; aw += fb.y;
            }
        }
        for (; t < n; t++) {
            int s = __shfl_sync(0xffffffffu, sj, t);
            uint2 r = x2[(size_t)s * 32 + lane];
            float2 fa = __half22float2(*reinterpret_cast<__half2*>(&r.x));
            float2 fb = __half22float2(*reinterpret_cast<__half2*>(&r.y));
            ax += fa.x; ay += fa.y; az += fb.x; aw += fb.y;
        }
    }
    float inv = 1.0f / (float)max(s1 - s0, 1);
    float4 o = make_float4(ax * inv, ay * inv, az * inv, aw * inv);
    reinterpret_cast<float4*>(outm)[(size_t)node * 32 + lane] = o;
}

// ---------------- final gather: out[n] = mean(p_fp16[src]) + z[n] ---------
__global__ void gather_final_h(const __half* __restrict__ ph,
                               const float* __restrict__ z,
                               const int* __restrict__ row_off,
                               const int* __restrict__ csr,
                               float* __restrict__ out) {
    int node = blockIdx.x * (blockDim.x >> 5) + (threadIdx.x >> 5);
    int lane = threadIdx.x & 31;
    if (node >= N_NODES) return;
    int s0 = row_off[node], s1 = row_off[node + 1];
    const uint2* p2 = reinterpret_cast<const uint2*>(ph);
    float ax = 0.f, ay = 0.f, az = 0.f, aw = 0.f;
    for (int j = s0; j < s1; j += 32) {
        int n = min(32, s1 - j);
        int sj = (lane < n) ? csr[j + lane] : 0;
        int t = 0;
        for (; t + 8 <= n; t += 8) {
            uint2 raw[8];
#pragma unroll
            for (int u = 0; u < 8; u++) {
                int s = __shfl_sync(0xffffffffu, sj, t + u);
                raw[u] = p2[(size_t)s * 32 + lane];
            }
#pragma unroll
            for (int u = 0; u < 8; u++) {
                float2 fa = __half22float2(*reinterpret_cast<__half2*>(&raw[u].x));
                float2 fb = __half22float2(*reinterpret_cast<__half2*>(&raw[u].y));
                ax += fa.x; ay += fa.y; az += fb.x; aw += fb.y;
            }
        }
        for (; t < n; t++) {
            int s = __shfl_sync(0xffffffffu, sj, t);
            uint2 r = p2[(size_t)s * 32 + lane];
            float2 fa = __half22float2(*reinterpret_cast<__half2*>(&r.x));
            float2 fb = __half22float2(*reinterpret_cast<__half2*>(&r.y));
            ax += fa.x; ay += fa.y; az += fb.x; aw += fb.y;
        }
    }
    float inv = 1.0f / (float)max(s1 - s0, 1);
    float4 zv = reinterpret_cast<const float4*>(z)[(size_t)node * 32 + lane];
    float4 o = make_float4(ax * inv + zv.x, ay * inv + zv.y,
                           az * inv + zv.z, aw * inv + zv.w);
    reinterpret_cast<float4*>(out)[(size_t)node * 32 + lane] = o;
}

// ---------------- bf16x3 mma.sync GEMM, double-buffered --------------------
// Virtual K' = 768 in 24 chunks of 32: A'=[Ahi|Ahi|Alo], B'=[Bhi|Blo|Bhi].
// Block tile 128x128 (grid.y picks n half). 8 warps: wm=wid&3, wn=wid>>2.
// mode 0: A=[mean1|x] (stride 128 each), out = relu(.+bias) -> Cf [M,256]
// mode 1: A=h (stride 256); n0==0 half -> p as fp16 into Cp [M,128];
//         n0==128 half -> z = .+bias as fp32 into Cf [M,128]
__global__ __launch_bounds__(256)
void sage_gemm_mma(const float* __restrict__ A1, const float* __restrict__ A2,
                   const __nv_bfloat16* __restrict__ BW,
                   const float* __restrict__ bias,
                   float* __restrict__ Cf, __half* __restrict__ Cp,
                   int M, int mode)
{
    __shared__ __align__(16) char sA[2][128 * 80];   // [row][32 bf16], 80B pitch
    __shared__ __align__(16) char sB[2][128 * 80];

    int tid = threadIdx.x;
    int lane = tid & 31, wid = tid >> 5;
    int wm = wid & 3, wn = wid >> 2;
    int m0 = blockIdx.x * 128, n0 = blockIdx.y * 128;

    uint32_t sAa[2] = { smem_u32(sA[0]), smem_u32(sA[1]) };
    uint32_t sBa[2] = { smem_u32(sB[0]), smem_u32(sB[1]) };

    int srow = tid >> 1, shalf = tid & 1;
    int grow = m0 + srow;
    int brow = tid >> 2, bq = tid & 3;

    float acc[2][8][4];
#pragma unroll
    for (int i = 0; i < 2; i++)
#pragma unroll
        for (int j = 0; j < 8; j++)
#pragma unroll
            for (int q = 0; q < 4; q++) acc[i][j][q] = 0.f;

    float4 pa[4];

#define LOAD_A(cc) do { \
    int kc = ((cc) & 7) * 32; \
    const float* Asrc; int astr, acol; \
    if (mode == 0) { \
        if (kc < 128) { Asrc = A1; acol = kc; } \
        else          { Asrc = A2; acol = kc - 128; } \
        astr = 128; \
    } else { Asrc = A1; astr = 256; acol = kc; } \
    if (grow < M) { \
        const float4* ap = reinterpret_cast<const float4*>( \
            Asrc + (size_t)grow * astr + acol + shalf * 16); \
        pa[0] = ap[0]; pa[1] = ap[1]; pa[2] = ap[2]; pa[3] = ap[3]; \
    } else { \
        pa[0] = pa[1] = pa[2] = pa[3] = make_float4(0.f, 0.f, 0.f, 0.f); \
    } \
} while (0)

#define STORE_A(cc, buf) do { \
    bool lo_ = ((cc) >> 3) == 2; \
    const float* f_ = reinterpret_cast<const float*>(pa); \
    uint32_t w_[8]; \
    _Pragma("unroll") \
    for (int i_ = 0; i_ < 8; i_++) { \
        float v0_ = f_[i_ * 2], v1_ = f_[i_ * 2 + 1]; \
        __nv_bfloat16 h0_ = __float2bfloat16(v0_); \
        __nv_bfloat16 h1_ = __float2bfloat16(v1_); \
        if (lo_) { \
            h0_ = __float2bfloat16(v0_ - __bfloat162float(h0_)); \
            h1_ = __float2bfloat16(v1_ - __bfloat162float(h1_)); \
        } \
        w_[i_] = (uint32_t)__bfloat16_as_ushort(h0_) | \
                 ((uint32_t)__bfloat16_as_ushort(h1_) << 16); \
    } \
    uint4* da_ = reinterpret_cast<uint4*>(sA[buf] + srow * 80 + shalf * 32); \
    da_[0] = make_uint4(w_[0], w_[1], w_[2], w_[3]); \
    da_[1] = make_uint4(w_[4], w_[5], w_[6], w_[7]); \
} while (0)

#define CP_B(cc, buf) do { \
    _Pragma("unroll") \
    for (int i_ = 0; i_ < 2; i_++) { \
        int r_ = brow + i_ * 64; \
        cp_async16(sBa[buf] + (uint32_t)r_ * 80 + bq * 16, \
                   BW + (size_t)(n0 + r_) * 768 + (cc) * 32 + bq * 8); \
    } \
    CP_COMMIT(); \
} while (0)

    LOAD_A(0);
    STORE_A(0, 0);
    CP_B(0, 0);
    LOAD_A(1);
    CP_WAIT0();
    __syncthreads();

    for (int c = 0; c < 24; c++) {
        int cb = c & 1;
        if (c < 23) {
            STORE_A(c + 1, cb ^ 1);
            CP_B(c + 1, cb ^ 1);
            if (c < 22) LOAD_A(c + 2);
        }

#pragma unroll
        for (int kh = 0; kh < 2; kh++) {
            uint32_t af[2][4], bf[8][2];
#pragma unroll
            for (int mt = 0; mt < 2; mt++)
                ldsm_x4(af[mt], sAa[cb] + (uint32_t)(wm * 32 + mt * 16 + (lane & 15)) * 80
                               + kh * 32 + (lane >> 4) * 16);
#pragma unroll
            for (int np = 0; np < 4; np++) {
                uint32_t q[4];
                int r = wn * 64 + np * 16 + (lane & 7) + ((lane >> 4) & 1) * 8;
                int cOff = ((lane >> 3) & 1) * 16;
                ldsm_x4(q, sBa[cb] + (uint32_t)r * 80 + kh * 32 + cOff);
                bf[np * 2][0] = q[0]; bf[np * 2][1] = q[1];
                bf[np * 2 + 1][0] = q[2]; bf[np * 2 + 1][1] = q[3];
            }
#pragma unroll
            for (int mt = 0; mt < 2; mt++)
#pragma unroll
                for (int nt = 0; nt < 8; nt++)
                    mma_bf16(acc[mt][nt], af[mt], bf[nt]);
        }

        CP_WAIT0();
        __syncthreads();
    }

    // ---- epilogue ----
    int g = lane >> 2, t = lane & 3;
#pragma unroll
    for (int mt = 0; mt < 2; mt++) {
        int r0 = m0 + wm * 32 + mt * 16 + g;
#pragma unroll
        for (int nt = 0; nt < 8; nt++) {
            int col = n0 + wn * 64 + nt * 8 + t * 2;
            if (mode == 0) {
                float bx = bias[col], by = bias[col + 1];
                float v0 = fmaxf(acc[mt][nt][0] + bx, 0.f);
                float v1 = fmaxf(acc[mt][nt][1] + by, 0.f);
                float v2 = fmaxf(acc[mt][nt][2] + bx, 0.f);
                float v3 = fmaxf(acc[mt][nt][3] + by, 0.f);
                if (r0 < M)
                    *reinterpret_cast<float2*>(Cf + (size_t)r0 * 256 + col) = make_float2(v0, v1);
                if (r0 + 8 < M)
                    *reinterpret_cast<float2*>(Cf + (size_t)(r0 + 8) * 256 + col) = make_float2(v2, v3);
            } else if (n0 == 0) {
                // p -> fp16
                __half2 h01 = __floats2half2_rn(acc[mt][nt][0], acc[mt][nt][1]);
                __half2 h23 = __floats2half2_rn(acc[mt][nt][2], acc[mt][nt][3]);
                if (r0 < M)
                    *reinterpret_cast<__half2*>(Cp + (size_t)r0 * 128 + col) = h01;
                if (r0 + 8 < M)
                    *reinterpret_cast<__half2*>(Cp + (size_t)(r0 + 8) * 128 + col) = h23;
            } else {
                // z -> fp32 with bias
                int zc = col - 128;
                float bx = bias[zc], by = bias[zc + 1];
                float v0 = acc[mt][nt][0] + bx, v1 = acc[mt][nt][1] + by;
                float v2 = acc[mt][nt][2] + bx, v3 = acc[mt][nt][3] + by;
                if (r0 < M)
                    *reinterpret_cast<float2*>(Cf + (size_t)r0 * 128 + zc) = make_float2(v0, v1);
                if (r0 + 8 < M)
                    *reinterpret_cast<float2*>(Cf + (size_t)(r0 + 8) * 128 + zc) = make_float2(v2, v3);
            }
        }
    }
}

// ---------------- launcher -------------------------------------------------
extern "C" void kernel_launch(void* const* d_in, const int* in_sizes, int n_in,
                              void* d_out, int out_size)
{
    const float* x   = (const float*)d_in[0];
    const void*  ei  = d_in[1];
    const float* Wl1 = (const float*)d_in[2];
    const float* bl1 = (const float*)d_in[3];
    const float* Wr1 = (const float*)d_in[4];
    const float* Wl2 = (const float*)d_in[5];
    const float* bl2 = (const float*)d_in[6];
    const float* Wr2 = (const float*)d_in[7];
    float* out = (float*)d_out;

    float *mean1, *h, *z;
    __half *ph, *xh;
    int *deg, *rowoff, *cursor, *csr, *bsum, *boff, *total;
    __nv_bfloat16 *BW1, *BW2;
    cudaGetSymbolAddress((void**)&mean1,  g_mean1);
    cudaGetSymbolAddress((void**)&h,      g_h);
    cudaGetSymbolAddress((void**)&z,      g_z);
    cudaGetSymbolAddress((void**)&ph,     g_ph);
    cudaGetSymbolAddress((void**)&xh,     g_xh);
    cudaGetSymbolAddress((void**)&deg,    g_deg);
    cudaGetSymbolAddress((void**)&rowoff, g_rowoff);
    cudaGetSymbolAddress((void**)&cursor, g_cursor);
    cudaGetSymbolAddress((void**)&csr,    g_csr);
    cudaGetSymbolAddress((void**)&bsum,   g_blocksum);
    cudaGetSymbolAddress((void**)&boff,   g_blockoff);
    cudaGetSymbolAddress((void**)&total,  g_total);
    cudaGetSymbolAddress((void**)&BW1,    g_BW1);
    cudaGetSymbolAddress((void**)&BW2,    g_BW2);

    // ---- setup (detect + zero deg + weight prep + x->fp16) ----
    {
        int nthreads = (N_NODES * IN_DIM) / 4;   // 1.6M, covers all sub-tasks
        setup_kernel<<<(nthreads + 255) / 256, 256>>>(
            (const int*)ei, x, Wl1, Wr1, Wl2, Wr2, deg, BW1, BW2, xh);
    }

    // ---- CSR build ----
    hist_kernel<<<(N_EDGES + 255) / 256, 256>>>(ei, deg);
    scan_phase1<<<N_SCAN_BLOCKS, SCAN_BLK>>>(deg, bsum);
    scan_phase2<<<1, 128>>>(bsum, boff, total);
    scan_phase3<<<N_SCAN_BLOCKS, SCAN_BLK>>>(deg, boff, total, rowoff, cursor);
    fill_kernel<<<(N_EDGES + 255) / 256, 256>>>(ei, cursor, csr);

    // ---- layer 1 ----
    {
        int wpb = 8;
        int blocks = (N_NODES + wpb - 1) / wpb;
        gather_mean_h<<<blocks, wpb * 32>>>(xh, rowoff, csr, mean1);
    }
    {
        dim3 grid((N_NODES + 127) / 128, 2);
        sage_gemm_mma<<<grid, 256>>>(mean1, x, BW1, bl1, h, nullptr, N_NODES, 0);
    }

    // ---- layer 2 ----
    {
        dim3 grid((N_NODES + 127) / 128, 2);
        sage_gemm_mma<<<grid, 256>>>(h, nullptr, BW2, bl2, z, ph, N_NODES, 1);
    }
    {
        int wpb = 8;
        int blocks = (N_NODES + wpb - 1) / wpb;
        gather_final_h<<<blocks, wpb * 32>>>(ph, z, rowoff, csr, out);
    }
}

// round 7
// speedup vs baseline: 5.6207x; 1.1733x over previous
#include <cuda_runtime.h>
#include <cuda_bf16.h>
#include <cuda_fp16.h>
#include <cstdint>

#define N_NODES 50000
#define N_EDGES 1600000
#define IN_DIM  128
#define HID_DIM 256
#define OUT_DIM 128

// ---------------- device scratch (no allocations allowed) ----------------
__device__ float g_mean1[(size_t)N_NODES * IN_DIM];   // mean-agg of x (fp32)
__device__ float g_z    [(size_t)N_NODES * OUT_DIM];  // z = h@Wr2 + b
__device__ __half g_ph  [(size_t)N_NODES * OUT_DIM];  // p = h@Wl2 (fp16)
__device__ __half g_xh  [(size_t)N_NODES * IN_DIM];   // x in fp16
__device__ int   g_deg  [N_NODES];
__device__ int   g_rowoff[N_NODES + 1];
__device__ int   g_cursor[N_NODES];
__device__ int   g_csr  [N_EDGES];
__device__ int   g_is64;
__device__ int   g_blocksum[128];
__device__ int   g_blockoff[128];
__device__ int   g_total;
// pre-built B' weights: [n=256][k'=768] bf16, k' = [Bhi(256) | Blo(256) | Bhi(256)]
__device__ __align__(16) __nv_bfloat16 g_BW1[256 * 768];
__device__ __align__(16) __nv_bfloat16 g_BW2[256 * 768];

// ---------------- mma helpers ----------------------------------------
__device__ __forceinline__ uint32_t smem_u32(const void* p) {
    uint32_t a;
    asm("{ .reg .u64 t; cvta.to.shared.u64 t, %1; cvt.u32.u64 %0, t; }"
        : "=r"(a) : "l"(p));
    return a;
}
__device__ __forceinline__ void ldsm_x4(uint32_t* r, uint32_t addr) {
    asm volatile("ldmatrix.sync.aligned.m8n8.x4.shared.b16 {%0,%1,%2,%3}, [%4];"
        : "=r"(r[0]), "=r"(r[1]), "=r"(r[2]), "=r"(r[3]) : "r"(addr));
}
__device__ __forceinline__ void mma_bf16(float* d, const uint32_t* a, const uint32_t* b) {
    asm volatile("mma.sync.aligned.m16n8k16.row.col.f32.bf16.bf16.f32 "
        "{%0,%1,%2,%3}, {%4,%5,%6,%7}, {%8,%9}, {%0,%1,%2,%3};"
        : "+f"(d[0]), "+f"(d[1]), "+f"(d[2]), "+f"(d[3])
        : "r"(a[0]), "r"(a[1]), "r"(a[2]), "r"(a[3]), "r"(b[0]), "r"(b[1]));
}
__device__ __forceinline__ void cp_async16(uint32_t dst, const void* src) {
    asm volatile("cp.async.cg.shared.global [%0], [%1], 16;"
                 :: "r"(dst), "l"(src) : "memory");
}
#define CP_COMMIT() asm volatile("cp.async.commit_group;" ::: "memory")
#define CP_WAIT0()  asm volatile("cp.async.wait_group 0;" ::: "memory")

// ---------------- setup: detect + zero deg + prep weights + x->fp16 -------
__global__ void setup_kernel(const int* __restrict__ ei32,
                             const float* __restrict__ x,
                             const float* __restrict__ Wl1, const float* __restrict__ Wr1,
                             const float* __restrict__ Wl2, const float* __restrict__ Wr2,
                             int* __restrict__ deg,
                             __nv_bfloat16* __restrict__ BW1,
                             __nv_bfloat16* __restrict__ BW2,
                             __half* __restrict__ xh) {
    int idx = blockIdx.x * blockDim.x + threadIdx.x;
    if (idx == 0)
        g_is64 = (ei32[1] == 0 && ei32[3] == 0 && ei32[5] == 0 && ei32[7] == 0) ? 1 : 0;
    if (idx < N_NODES) deg[idx] = 0;
    if (idx < 256 * 768) {
        int n = idx / 768, kp = idx % 768;
        int seg = kp >> 8, k = kp & 255;
        float w1 = (k < 128) ? Wl1[k * 256 + n] : Wr1[(k - 128) * 256 + n];
        float w2 = (n < 128) ? Wl2[k * 128 + n] : Wr2[k * 128 + (n - 128)];
        __nv_bfloat16 h1 = __float2bfloat16(w1);
        __nv_bfloat16 h2 = __float2bfloat16(w2);
        BW1[idx] = (seg == 1) ? __float2bfloat16(w1 - __bfloat162float(h1)) : h1;
        BW2[idx] = (seg == 1) ? __float2bfloat16(w2 - __bfloat162float(h2)) : h2;
    }
    if (idx < (N_NODES * IN_DIM) / 4) {
        float4 v = reinterpret_cast<const float4*>(x)[idx];
        __half2 a = __floats2half2_rn(v.x, v.y);
        __half2 b = __floats2half2_rn(v.z, v.w);
        reinterpret_cast<uint2*>(xh)[idx] =
            make_uint2(*reinterpret_cast<uint32_t*>(&a), *reinterpret_cast<uint32_t*>(&b));
    }
}

__global__ void hist_kernel(const void* __restrict__ ei, int* __restrict__ deg) {
    int i = blockIdx.x * blockDim.x + threadIdx.x;
    if (i >= N_EDGES) return;
    int dst;
    if (g_is64) dst = (int)reinterpret_cast<const long long*>(ei)[N_EDGES + i];
    else        dst = reinterpret_cast<const int*>(ei)[N_EDGES + i];
    atomicAdd(&deg[dst], 1);
}

// ---------------- 3-phase scan --------------------------------------------
#define SCAN_BLK 512
#define N_SCAN_BLOCKS ((N_NODES + SCAN_BLK - 1) / SCAN_BLK)  // 98

__global__ void scan_phase1(const int* __restrict__ deg, int* __restrict__ bsum) {
    __shared__ int sm[SCAN_BLK];
    int i = blockIdx.x * SCAN_BLK + threadIdx.x;
    sm[threadIdx.x] = (i < N_NODES) ? deg[i] : 0;
    __syncthreads();
    for (int s = SCAN_BLK / 2; s > 0; s >>= 1) {
        if (threadIdx.x < s) sm[threadIdx.x] += sm[threadIdx.x + s];
        __syncthreads();
    }
    if (threadIdx.x == 0) bsum[blockIdx.x] = sm[0];
}

__global__ void scan_phase2(const int* __restrict__ bsum, int* __restrict__ boff,
                            int* __restrict__ total) {
    __shared__ int sm[128];
    int t = threadIdx.x;
    sm[t] = (t < N_SCAN_BLOCKS) ? bsum[t] : 0;
    __syncthreads();
    for (int off = 1; off < 128; off <<= 1) {
        int v = (t >= off) ? sm[t - off] : 0;
        __syncthreads();
        sm[t] += v;
        __syncthreads();
    }
    if (t < N_SCAN_BLOCKS) boff[t] = (t == 0) ? 0 : sm[t - 1];
    if (t == 127) *total = sm[127];
}

__global__ void scan_phase3(const int* __restrict__ deg, const int* __restrict__ boff,
                            const int* __restrict__ total,
                            int* __restrict__ rowoff, int* __restrict__ cursor) {
    __shared__ int sm[SCAN_BLK];
    int i = blockIdx.x * SCAN_BLK + threadIdx.x;
    int v = (i < N_NODES) ? deg[i] : 0;
    sm[threadIdx.x] = v;
    __syncthreads();
    for (int off = 1; off < SCAN_BLK; off <<= 1) {
        int u = (threadIdx.x >= off) ? sm[threadIdx.x - off] : 0;
        __syncthreads();
        sm[threadIdx.x] += u;
        __syncthreads();
    }
    if (i < N_NODES) {
        int excl = boff[blockIdx.x] + sm[threadIdx.x] - v;
        rowoff[i] = excl;
        cursor[i] = excl;
    }
    if (blockIdx.x == gridDim.x - 1 && threadIdx.x == SCAN_BLK - 1)
        rowoff[N_NODES] = *total;
}

__global__ void fill_kernel(const void* __restrict__ ei,
                            int* __restrict__ cursor, int* __restrict__ csr) {
    int i = blockIdx.x * blockDim.x + threadIdx.x;
    if (i >= N_EDGES) return;
    int src, dst;
    if (g_is64) {
        const long long* e = reinterpret_cast<const long long*>(ei);
        src = (int)e[i]; dst = (int)e[N_EDGES + i];
    } else {
        const int* e = reinterpret_cast<const int*>(ei);
        src = e[i]; dst = e[N_EDGES + i];
    }
    int pos = atomicAdd(&cursor[dst], 1);
    csr[pos] = src;
}

// ---------------- gather-mean (fp16 src) -----------------------------------
__global__ void gather_mean_h(const __half* __restrict__ xh,
                              const int* __restrict__ row_off,
                              const int* __restrict__ csr,
                              float* __restrict__ outm) {
    int node = blockIdx.x * (blockDim.x >> 5) + (threadIdx.x >> 5);
    int lane = threadIdx.x & 31;
    if (node >= N_NODES) return;
    int s0 = row_off[node], s1 = row_off[node + 1];
    const uint2* x2 = reinterpret_cast<const uint2*>(xh);
    float ax = 0.f, ay = 0.f, az = 0.f, aw = 0.f;
    for (int j = s0; j < s1; j += 32) {
        int n = min(32, s1 - j);
        int sj = (lane < n) ? csr[j + lane] : 0;
        int t = 0;
        for (; t + 8 <= n; t += 8) {
            uint2 raw[8];
#pragma unroll
            for (int u = 0; u < 8; u++) {
                int s = __shfl_sync(0xffffffffu, sj, t + u);
                raw[u] = x2[(size_t)s * 32 + lane];
            }
#pragma unroll
            for (int u = 0; u < 8; u++) {
                float2 fa = __half22float2(*reinterpret_cast<__half2*>(&raw[u].x));
                float2 fb = __half22float2(*reinterpret_cast<__half2*>(&raw[u].y));
                ax += fa.x; ay += fa.y; az += fb.x; aw += fb.y;
            }
        }
        for (; t < n; t++) {
            int s = __shfl_sync(0xffffffffu, sj, t);
            uint2 r = x2[(size_t)s * 32 + lane];
            float2 fa = __half22float2(*reinterpret_cast<__half2*>(&r.x));
            float2 fb = __half22float2(*reinterpret_cast<__half2*>(&r.y));
            ax += fa.x; ay += fa.y; az += fb.x; aw += fb.y;
        }
    }
    float inv = 1.0f / (float)max(s1 - s0, 1);
    float4 o = make_float4(ax * inv, ay * inv, az * inv, aw * inv);
    reinterpret_cast<float4*>(outm)[(size_t)node * 32 + lane] = o;
}

// ---------------- final gather: out[n] = mean(p_fp16[src]) + z[n] ---------
__global__ void gather_final_h(const __half* __restrict__ ph,
                               const float* __restrict__ z,
                               const int* __restrict__ row_off,
                               const int* __restrict__ csr,
                               float* __restrict__ out) {
    int node = blockIdx.x * (blockDim.x >> 5) + (threadIdx.x >> 5);
    int lane = threadIdx.x & 31;
    if (node >= N_NODES) return;
    int s0 = row_off[node], s1 = row_off[node + 1];
    const uint2* p2 = reinterpret_cast<const uint2*>(ph);
    float ax = 0.f, ay = 0.f, az = 0.f, aw = 0.f;
    for (int j = s0; j < s1; j += 32) {
        int n = min(32, s1 - j);
        int sj = (lane < n) ? csr[j + lane] : 0;
        int t = 0;
        for (; t + 8 <= n; t += 8) {
            uint2 raw[8];
#pragma unroll
            for (int u = 0; u < 8; u++) {
                int s = __shfl_sync(0xffffffffu, sj, t + u);
                raw[u] = p2[(size_t)s * 32 + lane];
            }
#pragma unroll
            for (int u = 0; u < 8; u++) {
                float2 fa = __half22float2(*reinterpret_cast<__half2*>(&raw[u].x));
                float2 fb = __half22float2(*reinterpret_cast<__half2*>(&raw[u].y));
                ax += fa.x; ay += fa.y; az += fb.x; aw += fb.y;
            }
        }
        for (; t < n; t++) {
            int s = __shfl_sync(0xffffffffu, sj, t);
            uint2 r = p2[(size_t)s * 32 + lane];
            float2 fa = __half22float2(*reinterpret_cast<__half2*>(&r.x));
            float2 fb = __half22float2(*reinterpret_cast<__half2*>(&r.y));
            ax += fa.x; ay += fa.y; az += fb.x; aw += fb.y;
        }
    }
    float inv = 1.0f / (float)max(s1 - s0, 1);
    float4 zv = reinterpret_cast<const float4*>(z)[(size_t)node * 32 + lane];
    float4 o = make_float4(ax * inv + zv.x, ay * inv + zv.y,
                           az * inv + zv.z, aw * inv + zv.w);
    reinterpret_cast<float4*>(out)[(size_t)node * 32 + lane] = o;
}

// ---------------- fused layer1+layer2 GEMM ---------------------------------
// One block = 128 node-rows. 512 threads, 16 warps (wm=wid&3: 32 rows,
// wn=wid>>2: 64 cols). Loop1: h_tile = relu([mean1|x]@BW1' + bl1), kept in
// SMEM as bf16 hi/lo planes (pitch 528B). Loop2: (p|z) = h_tile @ BW2'.
// h never touches global memory.
#define PL_HI   0
#define PL_LO   67584
#define OFF_SA  135168             // + buf*10240  (128 rows x 80B)
#define OFF_SB  155648             // + buf*20480  (256 rows x 80B)
#define FUSED_SMEM 196608          // 192 KB

__global__ __launch_bounds__(512, 1)
void sage_fused(const float* __restrict__ A1, const float* __restrict__ A2,
                const __nv_bfloat16* __restrict__ BW1, const float* __restrict__ bl1,
                const __nv_bfloat16* __restrict__ BW2, const float* __restrict__ bl2,
                float* __restrict__ z, __half* __restrict__ ph, int M)
{
    extern __shared__ __align__(16) char smem[];
    uint32_t sbase = smem_u32(smem);

    int tid = threadIdx.x;
    int lane = tid & 31, wid = tid >> 5;
    int wm = wid & 3, wn = wid >> 2;        // wn in 0..3
    int m0 = blockIdx.x * 128;

    int srow = tid >> 2, squad = tid & 3;   // A staging: row, 16B quad of 64B
    int grow = m0 + srow;
    int bq = tid & 3;                        // B staging quad

    float acc[2][8][4];
#pragma unroll
    for (int i = 0; i < 2; i++)
#pragma unroll
        for (int j = 0; j < 8; j++)
#pragma unroll
            for (int q = 0; q < 4; q++) acc[i][j][q] = 0.f;

    float4 pa[2];

#define LOAD_A1(cc) do { \
    int kc = ((cc) & 7) * 32; \
    const float* Asrc; int acol; \
    if (kc < 128) { Asrc = A1; acol = kc; } \
    else          { Asrc = A2; acol = kc - 128; } \
    if (grow < M) { \
        const float4* ap = reinterpret_cast<const float4*>( \
            Asrc + (size_t)grow * 128 + acol + squad * 8); \
        pa[0] = ap[0]; pa[1] = ap[1]; \
    } else { \
        pa[0] = pa[1] = make_float4(0.f, 0.f, 0.f, 0.f); \
    } \
} while (0)

#define STORE_A1(cc, buf) do { \
    bool lo_ = ((cc) >> 3) == 2; \
    const float* f_ = reinterpret_cast<const float*>(pa); \
    uint32_t w_[4]; \
    _Pragma("unroll") \
    for (int i_ = 0; i_ < 4; i_++) { \
        float v0_ = f_[i_ * 2], v1_ = f_[i_ * 2 + 1]; \
        __nv_bfloat16 h0_ = __float2bfloat16(v0_); \
        __nv_bfloat16 h1_ = __float2bfloat16(v1_); \
        if (lo_) { \
            h0_ = __float2bfloat16(v0_ - __bfloat162float(h0_)); \
            h1_ = __float2bfloat16(v1_ - __bfloat162float(h1_)); \
        } \
        w_[i_] = (uint32_t)__bfloat16_as_ushort(h0_) | \
                 ((uint32_t)__bfloat16_as_ushort(h1_) << 16); \
    } \
    *reinterpret_cast<uint4*>(smem + OFF_SA + (buf) * 10240 + srow * 80 + squad * 16) = \
        make_uint4(w_[0], w_[1], w_[2], w_[3]); \
} while (0)

#define CP_B(BW, cc, buf) do { \
    _Pragma("unroll") \
    for (int i_ = 0; i_ < 2; i_++) { \
        int r_ = (tid >> 2) + i_ * 128; \
        cp_async16(sbase + OFF_SB + (buf) * 20480 + (uint32_t)r_ * 80 + bq * 16, \
                   (BW) + (size_t)r_ * 768 + (cc) * 32 + bq * 8); \
    } \
    CP_COMMIT(); \
} while (0)

#define LOAD_FRAGS_B(buf, kh, bf) do { \
    _Pragma("unroll") \
    for (int np = 0; np < 4; np++) { \
        uint32_t q_[4]; \
        int r_ = wn * 64 + np * 16 + (lane & 7) + ((lane >> 4) & 1) * 8; \
        int cOff_ = ((lane >> 3) & 1) * 16; \
        ldsm_x4(q_, sbase + OFF_SB + (buf) * 20480 + (uint32_t)r_ * 80 + (kh) * 32 + cOff_); \
        (bf)[np * 2][0] = q_[0]; (bf)[np * 2][1] = q_[1]; \
        (bf)[np * 2 + 1][0] = q_[2]; (bf)[np * 2 + 1][1] = q_[3]; \
    } \
} while (0)

    // ================= loop 1: h = relu([mean1|x] @ BW1' + bl1) ===========
    LOAD_A1(0);
    STORE_A1(0, 0);
    CP_B(BW1, 0, 0);
    LOAD_A1(1);
    CP_WAIT0();
    __syncthreads();

    for (int c = 0; c < 24; c++) {
        int cb = c & 1;
        if (c < 23) {
            STORE_A1(c + 1, cb ^ 1);
            CP_B(BW1, c + 1, cb ^ 1);
            if (c < 22) LOAD_A1(c + 2);
        }
#pragma unroll
        for (int kh = 0; kh < 2; kh++) {
            uint32_t af[2][4], bf[8][2];
#pragma unroll
            for (int mt = 0; mt < 2; mt++)
                ldsm_x4(af[mt], sbase + OFF_SA + cb * 10240
                        + (uint32_t)(wm * 32 + mt * 16 + (lane & 15)) * 80
                        + kh * 32 + (lane >> 4) * 16);
            LOAD_FRAGS_B(cb, kh, bf);
#pragma unroll
            for (int mt = 0; mt < 2; mt++)
#pragma unroll
                for (int nt = 0; nt < 8; nt++)
                    mma_bf16(acc[mt][nt], af[mt], bf[nt]);
        }
        CP_WAIT0();
        __syncthreads();
    }

    // ---- epilogue 1: bias + relu, split to bf16 hi/lo planes in SMEM ----
    {
        int g = lane >> 2, t = lane & 3;
#pragma unroll
        for (int mt = 0; mt < 2; mt++) {
            int r0 = wm * 32 + mt * 16 + g;
#pragma unroll
            for (int nt = 0; nt < 8; nt++) {
                int col = wn * 64 + nt * 8 + t * 2;
                float bx = bl1[col], by = bl1[col + 1];
                float v0 = fmaxf(acc[mt][nt][0] + bx, 0.f);
                float v1 = fmaxf(acc[mt][nt][1] + by, 0.f);
                float v2 = fmaxf(acc[mt][nt][2] + bx, 0.f);
                float v3 = fmaxf(acc[mt][nt][3] + by, 0.f);
                __nv_bfloat16 h0 = __float2bfloat16(v0), h1 = __float2bfloat16(v1);
                __nv_bfloat16 h2 = __float2bfloat16(v2), h3 = __float2bfloat16(v3);
                uint32_t hi01 = (uint32_t)__bfloat16_as_ushort(h0) |
                                ((uint32_t)__bfloat16_as_ushort(h1) << 16);
                uint32_t hi23 = (uint32_t)__bfloat16_as_ushort(h2) |
                                ((uint32_t)__bfloat16_as_ushort(h3) << 16);
                __nv_bfloat16 l0 = __float2bfloat16(v0 - __bfloat162float(h0));
                __nv_bfloat16 l1 = __float2bfloat16(v1 - __bfloat162float(h1));
                __nv_bfloat16 l2 = __float2bfloat16(v2 - __bfloat162float(h2));
                __nv_bfloat16 l3 = __float2bfloat16(v3 - __bfloat162float(h3));
                uint32_t lo01 = (uint32_t)__bfloat16_as_ushort(l0) |
                                ((uint32_t)__bfloat16_as_ushort(l1) << 16);
                uint32_t lo23 = (uint32_t)__bfloat16_as_ushort(l2) |
                                ((uint32_t)__bfloat16_as_ushort(l3) << 16);
                *reinterpret_cast<uint32_t*>(smem + PL_HI + r0 * 528 + col * 2) = hi01;
                *reinterpret_cast<uint32_t*>(smem + PL_HI + (r0 + 8) * 528 + col * 2) = hi23;
                *reinterpret_cast<uint32_t*>(smem + PL_LO + r0 * 528 + col * 2) = lo01;
                *reinterpret_cast<uint32_t*>(smem + PL_LO + (r0 + 8) * 528 + col * 2) = lo23;
            }
        }
    }

    // re-zero accumulators for loop 2
#pragma unroll
    for (int i = 0; i < 2; i++)
#pragma unroll
        for (int j = 0; j < 8; j++)
#pragma unroll
            for (int q = 0; q < 4; q++) acc[i][j][q] = 0.f;

    __syncthreads();

    // ================= loop 2: (p|z) = h_tile @ BW2' =======================
    CP_B(BW2, 0, 0);
    CP_WAIT0();
    __syncthreads();

    for (int c = 0; c < 24; c++) {
        int cb = c & 1;
        if (c < 23) CP_B(BW2, c + 1, cb ^ 1);

        uint32_t plane = (c < 16) ? PL_HI : PL_LO;
        uint32_t koff = (uint32_t)(c & 7) * 64;
#pragma unroll
        for (int kh = 0; kh < 2; kh++) {
            uint32_t af[2][4], bf[8][2];
#pragma unroll
            for (int mt = 0; mt < 2; mt++)
                ldsm_x4(af[mt], sbase + plane
                        + (uint32_t)(wm * 32 + mt * 16 + (lane & 15)) * 528
                        + koff + kh * 32 + (lane >> 4) * 16);
            LOAD_FRAGS_B(cb, kh, bf);
#pragma unroll
            for (int mt = 0; mt < 2; mt++)
#pragma unroll
                for (int nt = 0; nt < 8; nt++)
                    mma_bf16(acc[mt][nt], af[mt], bf[nt]);
        }
        CP_WAIT0();
        __syncthreads();
    }

    // ---- epilogue 2: p (fp16, cols<128) and z (fp32 + bias, cols>=128) ----
    {
        int g = lane >> 2, t = lane & 3;
#pragma unroll
        for (int mt = 0; mt < 2; mt++) {
            int r0 = m0 + wm * 32 + mt * 16 + g;
#pragma unroll
            for (int nt = 0; nt < 8; nt++) {
                int col = wn * 64 + nt * 8 + t * 2;
                if (col < 128) {
                    __half2 h01 = __floats2half2_rn(acc[mt][nt][0], acc[mt][nt][1]);
                    __half2 h23 = __floats2half2_rn(acc[mt][nt][2], acc[mt][nt][3]);
                    if (r0 < M)
                        *reinterpret_cast<__half2*>(ph + (size_t)r0 * 128 + col) = h01;
                    if (r0 + 8 < M)
                        *reinterpret_cast<__half2*>(ph + (size_t)(r0 + 8) * 128 + col) = h23;
                } else {
                    int zc = col - 128;
                    float bx = bl2[zc], by = bl2[zc + 1];
                    float v0 = acc[mt][nt][0] + bx, v1 = acc[mt][nt][1] + by;
                    float v2 = acc[mt][nt][2] + bx, v3 = acc[mt][nt][3] + by;
                    if (r0 < M)
                        *reinterpret_cast<float2*>(z + (size_t)r0 * 128 + zc) = make_float2(v0, v1);
                    if (r0 + 8 < M)
                        *reinterpret_cast<float2*>(z + (size_t)(r0 + 8) * 128 + zc) = make_float2(v2, v3);
                }
            }
        }
    }
}

// ---------------- launcher -------------------------------------------------
extern "C" void kernel_launch(void* const* d_in, const int* in_sizes, int n_in,
                              void* d_out, int out_size)
{
    const float* x   = (const float*)d_in[0];
    const void*  ei  = d_in[1];
    const float* Wl1 = (const float*)d_in[2];
    const float* bl1 = (const float*)d_in[3];
    const float* Wr1 = (const float*)d_in[4];
    const float* Wl2 = (const float*)d_in[5];
    const float* bl2 = (const float*)d_in[6];
    const float* Wr2 = (const float*)d_in[7];
    float* out = (float*)d_out;

    float *mean1, *z;
    __half *ph, *xh;
    int *deg, *rowoff, *cursor, *csr, *bsum, *boff, *total;
    __nv_bfloat16 *BW1, *BW2;
    cudaGetSymbolAddress((void**)&mean1,  g_mean1);
    cudaGetSymbolAddress((void**)&z,      g_z);
    cudaGetSymbolAddress((void**)&ph,     g_ph);
    cudaGetSymbolAddress((void**)&xh,     g_xh);
    cudaGetSymbolAddress((void**)&deg,    g_deg);
    cudaGetSymbolAddress((void**)&rowoff, g_rowoff);
    cudaGetSymbolAddress((void**)&cursor, g_cursor);
    cudaGetSymbolAddress((void**)&csr,    g_csr);
    cudaGetSymbolAddress((void**)&bsum,   g_blocksum);
    cudaGetSymbolAddress((void**)&boff,   g_blockoff);
    cudaGetSymbolAddress((void**)&total,  g_total);
    cudaGetSymbolAddress((void**)&BW1,    g_BW1);
    cudaGetSymbolAddress((void**)&BW2,    g_BW2);

    cudaFuncSetAttribute(sage_fused, cudaFuncAttributeMaxDynamicSharedMemorySize,
                         FUSED_SMEM);

    // ---- setup (detect + zero deg + weight prep + x->fp16) ----
    {
        int nthreads = (N_NODES * IN_DIM) / 4;
        setup_kernel<<<(nthreads + 255) / 256, 256>>>(
            (const int*)ei, x, Wl1, Wr1, Wl2, Wr2, deg, BW1, BW2, xh);
    }

    // ---- CSR build ----
    hist_kernel<<<(N_EDGES + 255) / 256, 256>>>(ei, deg);
    scan_phase1<<<N_SCAN_BLOCKS, SCAN_BLK>>>(deg, bsum);
    scan_phase2<<<1, 128>>>(bsum, boff, total);
    scan_phase3<<<N_SCAN_BLOCKS, SCAN_BLK>>>(deg, boff, total, rowoff, cursor);
    fill_kernel<<<(N_EDGES + 255) / 256, 256>>>(ei, cursor, csr);

    // ---- layer 1 aggregation ----
    {
        int wpb = 8;
        int blocks = (N_NODES + wpb - 1) / wpb;
        gather_mean_h<<<blocks, wpb * 32>>>(xh, rowoff, csr, mean1);
    }

    // ---- fused layer1+layer2 GEMM ----
    {
        int grid = (N_NODES + 127) / 128;
        sage_fused<<<grid, 512, FUSED_SMEM>>>(mean1, x, BW1, bl1, BW2, bl2,
                                              z, ph, N_NODES);
    }

    // ---- final aggregation ----
    {
        int wpb = 8;
        int blocks = (N_NODES + wpb - 1) / wpb;
        gather_final_h<<<blocks, wpb * 32>>>(ph, z, rowoff, csr, out);
    }
}